// round 1
// baseline (speedup 1.0000x reference)
#include <cuda_runtime.h>
#include <math.h>

#define EMBED   1024
#define RANK    8
#define HEADS   16
#define HDIM    64
#define NBATCH  2
#define SEQ     2048
#define TOKENS  (NBATCH*SEQ)   // 4096
#define LORA_SCALE 2.0f

// ---------------- scratch (device globals, no allocation) ----------------
__device__ float g_Weff_q[EMBED*EMBED];
__device__ float g_Weff_k[EMBED*EMBED];
__device__ float g_Weff_v[EMBED*EMBED];
__device__ float g_Weff_o[EMBED*EMBED];
__device__ float g_Q[TOKENS*EMBED];
__device__ float g_K[TOKENS*EMBED];
__device__ float g_V[TOKENS*EMBED];
__device__ float g_attn[TOKENS*EMBED];

// ---------------- fold: Weff = W + 2 * B @ A ----------------
__global__ void fold_kernel(const float* __restrict__ W,
                            const float* __restrict__ A,
                            const float* __restrict__ B,
                            float* __restrict__ Weff) {
    int idx = blockIdx.x * blockDim.x + threadIdx.x;
    if (idx >= EMBED*EMBED) return;
    int o = idx >> 10;
    int i = idx & (EMBED-1);
    float s = 0.f;
#pragma unroll
    for (int r = 0; r < RANK; r++)
        s = fmaf(B[o*RANK + r], A[r*EMBED + i], s);
    Weff[idx] = W[idx] + LORA_SCALE * s;
}

// ---------------- SGEMM: C[M,N] = A[M,K] @ Bw[N,K]^T + bias ----------------
#define BM 128
#define BN 128
#define BKK 8
__global__ __launch_bounds__(256)
void sgemm_bias(const float* __restrict__ A,
                const float* __restrict__ Bw,
                const float* __restrict__ bias,
                float* __restrict__ C, int M) {
    const int K = EMBED, N = EMBED;
    __shared__ __align__(16) float As[BKK][BM];
    __shared__ __align__(16) float Bs[BKK][BN];

    int m0 = blockIdx.y * BM;
    int n0 = blockIdx.x * BN;
    int tid = threadIdx.x;
    int tx = tid & 15;      // 0..15 -> n sub-tile
    int ty = tid >> 4;      // 0..15 -> m sub-tile

    float acc[8][8];
#pragma unroll
    for (int i = 0; i < 8; i++)
#pragma unroll
        for (int j = 0; j < 8; j++) acc[i][j] = 0.f;

    int lr = tid >> 1;          // 0..127
    int lc = (tid & 1) * 4;     // 0 or 4

    for (int k0 = 0; k0 < K; k0 += BKK) {
        float4 av = *reinterpret_cast<const float4*>(&A [(m0 + lr) * K + k0 + lc]);
        float4 bv = *reinterpret_cast<const float4*>(&Bw[(n0 + lr) * K + k0 + lc]);
        As[lc+0][lr] = av.x; As[lc+1][lr] = av.y; As[lc+2][lr] = av.z; As[lc+3][lr] = av.w;
        Bs[lc+0][lr] = bv.x; Bs[lc+1][lr] = bv.y; Bs[lc+2][lr] = bv.z; Bs[lc+3][lr] = bv.w;
        __syncthreads();

#pragma unroll
        for (int kk = 0; kk < BKK; kk++) {
            float4 a0 = *reinterpret_cast<const float4*>(&As[kk][ty*8]);
            float4 a1 = *reinterpret_cast<const float4*>(&As[kk][ty*8+4]);
            float4 b0 = *reinterpret_cast<const float4*>(&Bs[kk][tx*8]);
            float4 b1 = *reinterpret_cast<const float4*>(&Bs[kk][tx*8+4]);
            float ra[8] = {a0.x,a0.y,a0.z,a0.w,a1.x,a1.y,a1.z,a1.w};
            float rb[8] = {b0.x,b0.y,b0.z,b0.w,b1.x,b1.y,b1.z,b1.w};
#pragma unroll
            for (int i = 0; i < 8; i++)
#pragma unroll
                for (int j = 0; j < 8; j++)
                    acc[i][j] = fmaf(ra[i], rb[j], acc[i][j]);
        }
        __syncthreads();
    }

    float bvreg[8];
#pragma unroll
    for (int j = 0; j < 8; j++) bvreg[j] = bias[n0 + tx*8 + j];

#pragma unroll
    for (int i = 0; i < 8; i++) {
        int m = m0 + ty*8 + i;
#pragma unroll
        for (int j0 = 0; j0 < 8; j0 += 4) {
            float4 v;
            v.x = acc[i][j0+0] + bvreg[j0+0];
            v.y = acc[i][j0+1] + bvreg[j0+1];
            v.z = acc[i][j0+2] + bvreg[j0+2];
            v.w = acc[i][j0+3] + bvreg[j0+3];
            *reinterpret_cast<float4*>(&C[m*N + n0 + tx*8 + j0]) = v;
        }
    }
}

// ---------------- attention: flash-style fp32 ----------------
// grid: (SEQ/64, HEADS, NBATCH), block: 256 threads
// Each thread owns 1 query row (4 lanes per q), 16 strided key columns.
#define BQ 64
#define BKT 64
#define LDSS 68   // padded stride, conflict-free for the access patterns below

__global__ __launch_bounds__(256)
void attn_kernel(float* __restrict__ out) {
    extern __shared__ float sm[];
    float* Qs = sm;                       // [64][68]
    float* Ks = sm + BQ*LDSS;             // [64][68], reused as P
    float* Vs = sm + 2*BQ*LDSS;           // [64][68]

    const float* Qg = g_Q;
    const float* Kg = g_K;
    const float* Vg = g_V;

    int qt = blockIdx.x, h = blockIdx.y, n = blockIdx.z;
    int tid = threadIdx.x;
    int q  = tid >> 2;     // 0..63
    int lg = tid & 3;      // 0..3

    int base_q_tok = n*SEQ + qt*BQ;
    int col0 = h*HDIM;

    int lr = tid >> 4;          // 0..15
    int lc = (tid & 15) * 4;    // 0..60

    // load Q tile, pre-scaled by 1/sqrt(64)
#pragma unroll
    for (int p = 0; p < 4; p++) {
        int r = lr + p*16;
        float4 v = *reinterpret_cast<const float4*>(&Qg[(base_q_tok + r)*EMBED + col0 + lc]);
        Qs[r*LDSS + lc+0] = v.x * 0.125f;
        Qs[r*LDSS + lc+1] = v.y * 0.125f;
        Qs[r*LDSS + lc+2] = v.z * 0.125f;
        Qs[r*LDSS + lc+3] = v.w * 0.125f;
    }

    float m_prev = -1e30f;
    float l = 0.f;
    float accv[16];
#pragma unroll
    for (int i = 0; i < 16; i++) accv[i] = 0.f;

    for (int kt = 0; kt < SEQ/BKT; kt++) {
        int base_k_tok = n*SEQ + kt*BKT;
        __syncthreads();   // prior P/V reads done before overwrite
#pragma unroll
        for (int p = 0; p < 4; p++) {
            int r = lr + p*16;
            float4 kv = *reinterpret_cast<const float4*>(&Kg[(base_k_tok + r)*EMBED + col0 + lc]);
            Ks[r*LDSS + lc+0] = kv.x; Ks[r*LDSS + lc+1] = kv.y;
            Ks[r*LDSS + lc+2] = kv.z; Ks[r*LDSS + lc+3] = kv.w;
            float4 vv = *reinterpret_cast<const float4*>(&Vg[(base_k_tok + r)*EMBED + col0 + lc]);
            Vs[r*LDSS + lc+0] = vv.x; Vs[r*LDSS + lc+1] = vv.y;
            Vs[r*LDSS + lc+2] = vv.z; Vs[r*LDSS + lc+3] = vv.w;
        }
        __syncthreads();

        // scores: s[j] for kc = 4*j + lg
        float s[16];
#pragma unroll
        for (int j = 0; j < 16; j++) s[j] = 0.f;
        for (int d0 = 0; d0 < HDIM; d0 += 16) {
            float qd[16];
#pragma unroll
            for (int dd = 0; dd < 16; dd++) qd[dd] = Qs[q*LDSS + d0 + dd];
#pragma unroll
            for (int j = 0; j < 16; j++) {
                int kc = 4*j + lg;
                float a = s[j];
#pragma unroll
                for (int dd = 0; dd < 16; dd++)
                    a = fmaf(qd[dd], Ks[kc*LDSS + d0 + dd], a);
                s[j] = a;
            }
        }

        // online softmax (4 lanes share one q)
        float mloc = s[0];
#pragma unroll
        for (int j = 1; j < 16; j++) mloc = fmaxf(mloc, s[j]);
        mloc = fmaxf(mloc, __shfl_xor_sync(0xffffffffu, mloc, 1));
        mloc = fmaxf(mloc, __shfl_xor_sync(0xffffffffu, mloc, 2));
        float m_new = fmaxf(m_prev, mloc);
        float alpha = __expf(m_prev - m_new);

        float psum = 0.f;
#pragma unroll
        for (int j = 0; j < 16; j++) {
            s[j] = __expf(s[j] - m_new);
            psum += s[j];
        }
        psum += __shfl_xor_sync(0xffffffffu, psum, 1);
        psum += __shfl_xor_sync(0xffffffffu, psum, 2);
        l = l * alpha + psum;
        m_prev = m_new;

        __syncthreads();   // all S reads of Ks complete
#pragma unroll
        for (int j = 0; j < 16; j++)
            Ks[q*LDSS + 4*j + lg] = s[j];   // P tile
        __syncthreads();

#pragma unroll
        for (int i = 0; i < 16; i++) accv[i] *= alpha;
        for (int k = 0; k < BKT; k++) {
            float p = Ks[q*LDSS + k];
#pragma unroll
            for (int i = 0; i < 16; i++)
                accv[i] = fmaf(p, Vs[k*LDSS + 4*i + lg], accv[i]);
        }
    }

    float inv = 1.f / l;
#pragma unroll
    for (int i = 0; i < 16; i++)
        out[(base_q_tok + q)*EMBED + col0 + 4*i + lg] = accv[i] * inv;
}

// ---------------- launch ----------------
extern "C" void kernel_launch(void* const* d_in, const int* in_sizes, int n_in,
                              void* d_out, int out_size) {
    const float* x  = (const float*)d_in[0];
    const float* Wq = (const float*)d_in[1];
    const float* bq = (const float*)d_in[2];
    const float* Aq = (const float*)d_in[3];
    const float* Bq = (const float*)d_in[4];
    const float* Wk = (const float*)d_in[5];
    const float* bk = (const float*)d_in[6];
    const float* Ak = (const float*)d_in[7];
    const float* Bk = (const float*)d_in[8];
    const float* Wv = (const float*)d_in[9];
    const float* bv = (const float*)d_in[10];
    const float* Av = (const float*)d_in[11];
    const float* Bv = (const float*)d_in[12];
    const float* Wo = (const float*)d_in[13];
    const float* bo = (const float*)d_in[14];
    const float* Ao = (const float*)d_in[15];
    const float* Bo = (const float*)d_in[16];
    float* out = (float*)d_out;

    float *Weff_q, *Weff_k, *Weff_v, *Weff_o, *Q, *K, *V, *attn;
    cudaGetSymbolAddress((void**)&Weff_q, g_Weff_q);
    cudaGetSymbolAddress((void**)&Weff_k, g_Weff_k);
    cudaGetSymbolAddress((void**)&Weff_v, g_Weff_v);
    cudaGetSymbolAddress((void**)&Weff_o, g_Weff_o);
    cudaGetSymbolAddress((void**)&Q, g_Q);
    cudaGetSymbolAddress((void**)&K, g_K);
    cudaGetSymbolAddress((void**)&V, g_V);
    cudaGetSymbolAddress((void**)&attn, g_attn);

    // 1) fold LoRA into effective weights
    int fold_blocks = (EMBED*EMBED + 255) / 256;
    fold_kernel<<<fold_blocks, 256>>>(Wq, Aq, Bq, Weff_q);
    fold_kernel<<<fold_blocks, 256>>>(Wk, Ak, Bk, Weff_k);
    fold_kernel<<<fold_blocks, 256>>>(Wv, Av, Bv, Weff_v);
    fold_kernel<<<fold_blocks, 256>>>(Wo, Ao, Bo, Weff_o);

    // 2) Q/K/V projections
    dim3 ggrid(EMBED/BN, TOKENS/BM);
    sgemm_bias<<<ggrid, 256>>>(x, Weff_q, bq, Q, TOKENS);
    sgemm_bias<<<ggrid, 256>>>(x, Weff_k, bk, K, TOKENS);
    sgemm_bias<<<ggrid, 256>>>(x, Weff_v, bv, V, TOKENS);

    // 3) attention
    size_t smem = 3 * BQ * LDSS * sizeof(float);   // 52224 bytes
    cudaFuncSetAttribute(attn_kernel, cudaFuncAttributeMaxDynamicSharedMemorySize, (int)smem);
    dim3 agrid(SEQ/BQ, HEADS, NBATCH);
    attn_kernel<<<agrid, 256, smem>>>(attn);

    // 4) output projection
    sgemm_bias<<<ggrid, 256>>>(attn, Weff_o, bo, out, TOKENS);
}

// round 2
// speedup vs baseline: 5.6885x; 5.6885x over previous
#include <cuda_runtime.h>
#include <math.h>
#include <stdint.h>

#define EMBED   1024
#define RANK    8
#define HEADS   16
#define HDIM    64
#define NBATCH  2
#define SEQ     2048
#define TOKENS  (NBATCH*SEQ)
#define LORA_SCALE 2.0f

// ---------------- scratch ----------------
__device__ float g_Weff[4][EMBED*EMBED];
__device__ float g_Q[TOKENS*EMBED];
__device__ float g_K[TOKENS*EMBED];
__device__ float g_V[TOKENS*EMBED];
__device__ float g_attn[TOKENS*EMBED];

// ---------------- tf32 helpers ----------------
__device__ __forceinline__ uint32_t f2tf(float f) {
    uint32_t u; asm("cvt.rna.tf32.f32 %0, %1;" : "=r"(u) : "f"(f)); return u;
}
__device__ __forceinline__ void mma_tf32(float c[4], const uint32_t a[4], const uint32_t b[2]) {
    asm volatile("mma.sync.aligned.m16n8k8.row.col.f32.tf32.tf32.f32 "
        "{%0,%1,%2,%3}, {%4,%5,%6,%7}, {%8,%9}, {%0,%1,%2,%3};"
        : "+f"(c[0]), "+f"(c[1]), "+f"(c[2]), "+f"(c[3])
        : "r"(a[0]), "r"(a[1]), "r"(a[2]), "r"(a[3]), "r"(b[0]), "r"(b[1]));
}

// ---------------- fold: Weff[z] = W + 2 * B @ A ----------------
__global__ void fold4_kernel(const float* __restrict__ W0, const float* __restrict__ A0, const float* __restrict__ B0,
                             const float* __restrict__ W1, const float* __restrict__ A1, const float* __restrict__ B1,
                             const float* __restrict__ W2, const float* __restrict__ A2, const float* __restrict__ B2,
                             const float* __restrict__ W3, const float* __restrict__ A3, const float* __restrict__ B3) {
    int z = blockIdx.y;
    const float *W, *A, *B;
    if (z == 0) { W = W0; A = A0; B = B0; }
    else if (z == 1) { W = W1; A = A1; B = B1; }
    else if (z == 2) { W = W2; A = A2; B = B2; }
    else { W = W3; A = A3; B = B3; }
    float* out = g_Weff[z];
    int idx = blockIdx.x * blockDim.x + threadIdx.x;
    int o = idx >> 10;
    int i = idx & (EMBED - 1);
    float s = 0.f;
#pragma unroll
    for (int r = 0; r < RANK; r++)
        s = fmaf(B[o*RANK + r], A[r*EMBED + i], s);
    out[idx] = W[idx] + LORA_SCALE * s;
}

// ---------------- tf32 GEMM: C[M,N] = A[M,K] @ Bw[N,K]^T + bias ----------------
// block 128x128, 128 threads (4 warps), warp tile 64x64
#define SST 136   // smem row stride (floats); 136%32==8 -> conflict-free frag reads
__global__ __launch_bounds__(128)
void gemm_tf32(const float* __restrict__ A, const float* __restrict__ Bw,
               const float* __restrict__ bias, float* __restrict__ C) {
    __shared__ uint32_t As[16][SST];   // [k][m]
    __shared__ uint32_t Bs[16][SST];   // [k][n]

    const int tid  = threadIdx.x;
    const int warp = tid >> 5, lane = tid & 31;
    const int g = lane >> 2, c = lane & 3;
    const int wm = (warp & 1) * 64, wn = (warp >> 1) * 64;
    const int m0 = blockIdx.y * 128, n0 = blockIdx.x * 128;

    float acc[4][8][4];
#pragma unroll
    for (int t = 0; t < 4; t++)
#pragma unroll
        for (int j = 0; j < 8; j++)
#pragma unroll
            for (int r = 0; r < 4; r++) acc[t][j][r] = 0.f;

    const float* Ap = A  + (m0 + tid) * EMBED;
    const float* Bp = Bw + (n0 + tid) * EMBED;

    float4 ra[4], rb[4];
#pragma unroll
    for (int p = 0; p < 4; p++) {
        ra[p] = *(const float4*)(Ap + p*4);
        rb[p] = *(const float4*)(Bp + p*4);
    }

    for (int k0 = 0; k0 < EMBED; k0 += 16) {
        // store current tile to smem (conflict-free: bank = (8i + tid)%32)
#pragma unroll
        for (int p = 0; p < 4; p++) {
            As[4*p+0][tid] = f2tf(ra[p].x); As[4*p+1][tid] = f2tf(ra[p].y);
            As[4*p+2][tid] = f2tf(ra[p].z); As[4*p+3][tid] = f2tf(ra[p].w);
            Bs[4*p+0][tid] = f2tf(rb[p].x); Bs[4*p+1][tid] = f2tf(rb[p].y);
            Bs[4*p+2][tid] = f2tf(rb[p].z); Bs[4*p+3][tid] = f2tf(rb[p].w);
        }
        __syncthreads();

        if (k0 + 16 < EMBED) {
#pragma unroll
            for (int p = 0; p < 4; p++) {
                ra[p] = *(const float4*)(Ap + k0 + 16 + p*4);
                rb[p] = *(const float4*)(Bp + k0 + 16 + p*4);
            }
        }

#pragma unroll
        for (int kk = 0; kk < 16; kk += 8) {
            uint32_t af[4][4], bf[8][2];
#pragma unroll
            for (int t = 0; t < 4; t++) {
                af[t][0] = As[kk+c  ][wm + 16*t + g];
                af[t][1] = As[kk+c  ][wm + 16*t + g + 8];
                af[t][2] = As[kk+c+4][wm + 16*t + g];
                af[t][3] = As[kk+c+4][wm + 16*t + g + 8];
            }
#pragma unroll
            for (int j = 0; j < 8; j++) {
                bf[j][0] = Bs[kk+c  ][wn + 8*j + g];
                bf[j][1] = Bs[kk+c+4][wn + 8*j + g];
            }
#pragma unroll
            for (int t = 0; t < 4; t++)
#pragma unroll
                for (int j = 0; j < 8; j++)
                    mma_tf32(acc[t][j], af[t], bf[j]);
        }
        __syncthreads();
    }

    // epilogue
#pragma unroll
    for (int j = 0; j < 8; j++) {
        int col = n0 + wn + 8*j + 2*c;
        float b0 = bias[col], b1 = bias[col + 1];
#pragma unroll
        for (int t = 0; t < 4; t++) {
            int row0 = m0 + wm + 16*t + g;
            float2 v0 = make_float2(acc[t][j][0] + b0, acc[t][j][1] + b1);
            float2 v1 = make_float2(acc[t][j][2] + b0, acc[t][j][3] + b1);
            *(float2*)(C + row0*EMBED + col)       = v0;
            *(float2*)(C + (row0+8)*EMBED + col)   = v1;
        }
    }
}

// ---------------- flash attention, tf32 mma ----------------
// 128 q per CTA, 8 warps (16 q each), kt tiles of 64 keys
#define AQ  128
#define KT  64
#define KST 72    // K/V smem stride: 72%32==8
#define PST 136   // P/Q smem stride
__global__ __launch_bounds__(256)
void attn_tf32(const float* __restrict__ Qg, const float* __restrict__ Kg,
               const float* __restrict__ Vg, float* __restrict__ Og) {
    extern __shared__ uint32_t smu[];
    uint32_t* Ks = smu;                 // [64][72]  K^T: [d][tok]
    uint32_t* Vs = smu + 64*KST;        // [64][72]  V:   [tok][d]
    uint32_t* Ps = smu + 2*64*KST;      // [64][136] P: [tok][q], aliases Qs [d][q]

    const int qt = blockIdx.x, h = blockIdx.y, nb = blockIdx.z;
    const int tid = threadIdx.x, warp = tid >> 5, lane = tid & 31;
    const int g = lane >> 2, c = lane & 3;
    const int q0 = warp * 16;
    const int base_q = nb*SEQ + qt*AQ;
    const int col0 = h * HDIM;

    // ---- load Q tile (transposed, scaled) into Ps area: Qs[d][q] ----
    {
        int q = tid & 127;
        int fh = tid >> 7;   // 0/1
        const float* src = Qg + (base_q + q)*EMBED + col0;
#pragma unroll
        for (int p = 0; p < 8; p++) {
            int fc = 2*p + fh;
            float4 v = *(const float4*)(src + fc*4);
            Ps[(4*fc+0)*PST + q] = f2tf(v.x * 0.125f);
            Ps[(4*fc+1)*PST + q] = f2tf(v.y * 0.125f);
            Ps[(4*fc+2)*PST + q] = f2tf(v.z * 0.125f);
            Ps[(4*fc+3)*PST + q] = f2tf(v.w * 0.125f);
        }
    }
    __syncthreads();

    // ---- Q fragments to registers (held for entire kt loop) ----
    uint32_t qf[8][4];
#pragma unroll
    for (int ks = 0; ks < 8; ks++) {
        qf[ks][0] = Ps[(8*ks+c  )*PST + q0 + g];
        qf[ks][1] = Ps[(8*ks+c  )*PST + q0 + g + 8];
        qf[ks][2] = Ps[(8*ks+c+4)*PST + q0 + g];
        qf[ks][3] = Ps[(8*ks+c+4)*PST + q0 + g + 8];
    }

    float of[8][4];
#pragma unroll
    for (int j = 0; j < 8; j++)
#pragma unroll
        for (int r = 0; r < 4; r++) of[j][r] = 0.f;
    float m_lo = -1e30f, m_hi = -1e30f, l_lo = 0.f, l_hi = 0.f;

    for (int kt = 0; kt < SEQ/KT; kt++) {
        __syncthreads();   // prior PV reads of Ks/Vs done; Q frags extracted
        const int base_k = nb*SEQ + kt*KT;

        // K tile transposed: Ks[d][tok]
        {
            int tok = tid & 63;
            const float* src = Kg + (base_k + tok)*EMBED + col0;
#pragma unroll
            for (int p = 0; p < 4; p++) {
                int fc = (tid >> 6) + 4*p;
                float4 v = *(const float4*)(src + fc*4);
                Ks[(4*fc+0)*KST + tok] = f2tf(v.x);
                Ks[(4*fc+1)*KST + tok] = f2tf(v.y);
                Ks[(4*fc+2)*KST + tok] = f2tf(v.z);
                Ks[(4*fc+3)*KST + tok] = f2tf(v.w);
            }
        }
        // V tile: Vs[tok][d]
        {
            int fc = tid & 15;
#pragma unroll
            for (int p = 0; p < 4; p++) {
                int tok = (tid >> 4) + 16*p;
                float4 v = *(const float4*)(Vg + (base_k + tok)*EMBED + col0 + fc*4);
                uint4 u;
                u.x = f2tf(v.x); u.y = f2tf(v.y); u.z = f2tf(v.z); u.w = f2tf(v.w);
                *(uint4*)(&Vs[tok*KST + fc*4]) = u;
            }
        }
        __syncthreads();

        // ---- S = Q @ K^T ----
        float sf[8][4];
#pragma unroll
        for (int j = 0; j < 8; j++)
#pragma unroll
            for (int r = 0; r < 4; r++) sf[j][r] = 0.f;
#pragma unroll
        for (int ks = 0; ks < 8; ks++) {
#pragma unroll
            for (int j = 0; j < 8; j++) {
                uint32_t kb[2];
                kb[0] = Ks[(8*ks+c  )*KST + 8*j + g];
                kb[1] = Ks[(8*ks+c+4)*KST + 8*j + g];
                mma_tf32(sf[j], qf[ks], kb);
            }
        }

        // ---- online softmax (rows g and g+8) ----
        float mx_lo = -1e30f, mx_hi = -1e30f;
#pragma unroll
        for (int j = 0; j < 8; j++) {
            mx_lo = fmaxf(mx_lo, fmaxf(sf[j][0], sf[j][1]));
            mx_hi = fmaxf(mx_hi, fmaxf(sf[j][2], sf[j][3]));
        }
        mx_lo = fmaxf(mx_lo, __shfl_xor_sync(0xffffffffu, mx_lo, 1));
        mx_lo = fmaxf(mx_lo, __shfl_xor_sync(0xffffffffu, mx_lo, 2));
        mx_hi = fmaxf(mx_hi, __shfl_xor_sync(0xffffffffu, mx_hi, 1));
        mx_hi = fmaxf(mx_hi, __shfl_xor_sync(0xffffffffu, mx_hi, 2));

        float mn_lo = fmaxf(m_lo, mx_lo);
        float mn_hi = fmaxf(m_hi, mx_hi);
        float alpha_lo = __expf(m_lo - mn_lo);
        float alpha_hi = __expf(m_hi - mn_hi);

        float ps_lo = 0.f, ps_hi = 0.f;
#pragma unroll
        for (int j = 0; j < 8; j++) {
            sf[j][0] = __expf(sf[j][0] - mn_lo);
            sf[j][1] = __expf(sf[j][1] - mn_lo);
            sf[j][2] = __expf(sf[j][2] - mn_hi);
            sf[j][3] = __expf(sf[j][3] - mn_hi);
            ps_lo += sf[j][0] + sf[j][1];
            ps_hi += sf[j][2] + sf[j][3];
        }
        ps_lo += __shfl_xor_sync(0xffffffffu, ps_lo, 1);
        ps_lo += __shfl_xor_sync(0xffffffffu, ps_lo, 2);
        ps_hi += __shfl_xor_sync(0xffffffffu, ps_hi, 1);
        ps_hi += __shfl_xor_sync(0xffffffffu, ps_hi, 2);
        l_lo = l_lo * alpha_lo + ps_lo;
        l_hi = l_hi * alpha_hi + ps_hi;
        m_lo = mn_lo; m_hi = mn_hi;

        // ---- store P [tok][q]; own warp columns only ----
#pragma unroll
        for (int j = 0; j < 8; j++) {
            Ps[(8*j+2*c  )*PST + q0 + g]     = f2tf(sf[j][0]);
            Ps[(8*j+2*c+1)*PST + q0 + g]     = f2tf(sf[j][1]);
            Ps[(8*j+2*c  )*PST + q0 + g + 8] = f2tf(sf[j][2]);
            Ps[(8*j+2*c+1)*PST + q0 + g + 8] = f2tf(sf[j][3]);
        }
        __syncwarp();

        // ---- rescale O, then O += P @ V ----
#pragma unroll
        for (int j = 0; j < 8; j++) {
            of[j][0] *= alpha_lo; of[j][1] *= alpha_lo;
            of[j][2] *= alpha_hi; of[j][3] *= alpha_hi;
        }
#pragma unroll
        for (int ks = 0; ks < 8; ks++) {
            uint32_t pa[4];
            pa[0] = Ps[(8*ks+c  )*PST + q0 + g];
            pa[1] = Ps[(8*ks+c  )*PST + q0 + g + 8];
            pa[2] = Ps[(8*ks+c+4)*PST + q0 + g];
            pa[3] = Ps[(8*ks+c+4)*PST + q0 + g + 8];
#pragma unroll
            for (int dj = 0; dj < 8; dj++) {
                uint32_t vb[2];
                vb[0] = Vs[(8*ks+c  )*KST + 8*dj + g];
                vb[1] = Vs[(8*ks+c+4)*KST + 8*dj + g];
                mma_tf32(of[dj], pa, vb);
            }
        }
    }

    // ---- epilogue ----
    float il_lo = 1.f / l_lo, il_hi = 1.f / l_hi;
#pragma unroll
    for (int dj = 0; dj < 8; dj++) {
        int col = col0 + 8*dj + 2*c;
        float2 v0 = make_float2(of[dj][0]*il_lo, of[dj][1]*il_lo);
        float2 v1 = make_float2(of[dj][2]*il_hi, of[dj][3]*il_hi);
        *(float2*)(Og + (base_q + q0 + g    )*EMBED + col) = v0;
        *(float2*)(Og + (base_q + q0 + g + 8)*EMBED + col) = v1;
    }
}

// ---------------- launch ----------------
extern "C" void kernel_launch(void* const* d_in, const int* in_sizes, int n_in,
                              void* d_out, int out_size) {
    const float* x  = (const float*)d_in[0];
    const float* Wq = (const float*)d_in[1];
    const float* bq = (const float*)d_in[2];
    const float* Aq = (const float*)d_in[3];
    const float* Bq = (const float*)d_in[4];
    const float* Wk = (const float*)d_in[5];
    const float* bk = (const float*)d_in[6];
    const float* Ak = (const float*)d_in[7];
    const float* Bk = (const float*)d_in[8];
    const float* Wv = (const float*)d_in[9];
    const float* bv = (const float*)d_in[10];
    const float* Av = (const float*)d_in[11];
    const float* Bv = (const float*)d_in[12];
    const float* Wo = (const float*)d_in[13];
    const float* bo = (const float*)d_in[14];
    const float* Ao = (const float*)d_in[15];
    const float* Bo = (const float*)d_in[16];
    float* out = (float*)d_out;

    float *Weff, *Q, *K, *V, *attn;
    cudaGetSymbolAddress((void**)&Weff, g_Weff);
    cudaGetSymbolAddress((void**)&Q, g_Q);
    cudaGetSymbolAddress((void**)&K, g_K);
    cudaGetSymbolAddress((void**)&V, g_V);
    cudaGetSymbolAddress((void**)&attn, g_attn);
    float* Weff_q = Weff;
    float* Weff_k = Weff + EMBED*EMBED;
    float* Weff_v = Weff + 2*EMBED*EMBED;
    float* Weff_o = Weff + 3*EMBED*EMBED;

    // 1) fold LoRA into effective weights (all 4 in one launch)
    dim3 fgrid(EMBED*EMBED/256, 4);
    fold4_kernel<<<fgrid, 256>>>(Wq, Aq, Bq, Wk, Ak, Bk, Wv, Av, Bv, Wo, Ao, Bo);

    // 2) Q/K/V projections (tf32 tensor core GEMM)
    dim3 ggrid(EMBED/128, TOKENS/128);
    gemm_tf32<<<ggrid, 128>>>(x, Weff_q, bq, Q);
    gemm_tf32<<<ggrid, 128>>>(x, Weff_k, bk, K);
    gemm_tf32<<<ggrid, 128>>>(x, Weff_v, bv, V);

    // 3) attention
    size_t smem = (size_t)(2*64*KST + 64*PST) * sizeof(uint32_t);  // 71680 B
    static int attn_attr_set = 0;
    cudaFuncSetAttribute(attn_tf32, cudaFuncAttributeMaxDynamicSharedMemorySize, (int)smem);
    (void)attn_attr_set;
    dim3 agrid(SEQ/AQ, HEADS, NBATCH);
    attn_tf32<<<agrid, 256, smem>>>(Q, K, V, attn);

    // 4) output projection
    gemm_tf32<<<ggrid, 128>>>(attn, Weff_o, bo, out);
}

// round 3
// speedup vs baseline: 6.8734x; 1.2083x over previous
#include <cuda_runtime.h>
#include <math.h>
#include <stdint.h>

#define EMBED   1024
#define RANK    8
#define HEADS   16
#define HDIM    64
#define NBATCH  2
#define SEQ     2048
#define TOKENS  (NBATCH*SEQ)
#define LORA_SCALE 2.0f

// ---------------- scratch (tf32 bit patterns stored as uint32) ----------------
__device__ uint32_t g_Weff[4][EMBED*EMBED];
__device__ uint32_t g_xt[TOKENS*EMBED];
__device__ uint32_t g_Q[TOKENS*EMBED];
__device__ uint32_t g_K[TOKENS*EMBED];
__device__ uint32_t g_V[TOKENS*EMBED];
__device__ uint32_t g_attn[TOKENS*EMBED];

// ---------------- helpers ----------------
__device__ __forceinline__ uint32_t f2tf(float f) {
    uint32_t u; asm("cvt.rna.tf32.f32 %0, %1;" : "=r"(u) : "f"(f)); return u;
}
__device__ __forceinline__ void mma_tf32(float c[4], const uint32_t a[4], const uint32_t b[2]) {
    asm volatile("mma.sync.aligned.m16n8k8.row.col.f32.tf32.tf32.f32 "
        "{%0,%1,%2,%3}, {%4,%5,%6,%7}, {%8,%9}, {%0,%1,%2,%3};"
        : "+f"(c[0]), "+f"(c[1]), "+f"(c[2]), "+f"(c[3])
        : "r"(a[0]), "r"(a[1]), "r"(a[2]), "r"(a[3]), "r"(b[0]), "r"(b[1]));
}
__device__ __forceinline__ void ldsm4(uint32_t r[4], uint32_t addr) {
    asm volatile("ldmatrix.sync.aligned.m8n8.x4.shared.b16 {%0,%1,%2,%3}, [%4];"
        : "=r"(r[0]), "=r"(r[1]), "=r"(r[2]), "=r"(r[3]) : "r"(addr));
}
__device__ __forceinline__ void cp16(uint32_t saddr, const void* gaddr) {
    asm volatile("cp.async.cg.shared.global [%0], [%1], 16;" :: "r"(saddr), "l"(gaddr));
}
#define CP_COMMIT() asm volatile("cp.async.commit_group;")
template<int N> __device__ __forceinline__ void cp_wait() {
    asm volatile("cp.async.wait_group %0;" :: "n"(N));
}

// ---------------- xconv: fp32 -> tf32 bits ----------------
__global__ void xconv(const float4* __restrict__ in, uint4* __restrict__ out) {
    int i = blockIdx.x * blockDim.x + threadIdx.x;
    float4 v = in[i];
    uint4 u; u.x = f2tf(v.x); u.y = f2tf(v.y); u.z = f2tf(v.z); u.w = f2tf(v.w);
    out[i] = u;
}

// ---------------- fold: Weff[z] = tf32(W + 2 * B @ A) ----------------
__global__ void fold4_kernel(const float* __restrict__ W0, const float* __restrict__ A0, const float* __restrict__ B0,
                             const float* __restrict__ W1, const float* __restrict__ A1, const float* __restrict__ B1,
                             const float* __restrict__ W2, const float* __restrict__ A2, const float* __restrict__ B2,
                             const float* __restrict__ W3, const float* __restrict__ A3, const float* __restrict__ B3) {
    int z = blockIdx.y;
    const float *W, *A, *B;
    if (z == 0) { W = W0; A = A0; B = B0; }
    else if (z == 1) { W = W1; A = A1; B = B1; }
    else if (z == 2) { W = W2; A = A2; B = B2; }
    else { W = W3; A = A3; B = B3; }
    uint32_t* out = g_Weff[z];
    int idx = blockIdx.x * blockDim.x + threadIdx.x;
    int o = idx >> 10;
    int i = idx & (EMBED - 1);
    float s = 0.f;
#pragma unroll
    for (int r = 0; r < RANK; r++)
        s = fmaf(B[o*RANK + r], A[r*EMBED + i], s);
    out[idx] = f2tf(W[idx] + LORA_SCALE * s);
}

// ---------------- tf32 GEMM: C[M,N] = A[M,K] @ Bw[N,K]^T + bias ----------------
// CTA 128x128, 128 threads, warp tile 64x64, 3-stage cp.async, ldmatrix frags.
// smem per stage: A [128][20] + B [128][20] words (stride 20 -> conflict-free).
#define GST 20
#define GSTG (2*128*GST)    // 5120 words per stage
template<bool TF32OUT>
__global__ __launch_bounds__(128)
void gemm_tc(const uint32_t* __restrict__ A, const uint32_t* __restrict__ Wbase,
             const float* __restrict__ bz0, const float* __restrict__ bz1, const float* __restrict__ bz2,
             void* __restrict__ C0, void* __restrict__ C1, void* __restrict__ C2) {
    extern __shared__ uint32_t smg[];
    const int z = blockIdx.z;
    const uint32_t* Bw = Wbase + (size_t)z * (EMBED*EMBED);
    const float* bias = (z == 0) ? bz0 : (z == 1) ? bz1 : bz2;
    void* Cv = (z == 0) ? C0 : (z == 1) ? C1 : C2;

    const int tid = threadIdx.x, warp = tid >> 5, lane = tid & 31;
    const int g = lane >> 2, c = lane & 3;
    const int wm = (warp & 1) * 64, wn = (warp >> 1) * 64;
    const int m0 = blockIdx.y * 128, n0 = blockIdx.x * 128;

    const uint32_t sbase = (uint32_t)__cvta_generic_to_shared(smg);
    const uint32_t* Ag = A  + (size_t)(m0 + tid) * EMBED;
    const uint32_t* Bg = Bw + (size_t)(n0 + tid) * EMBED;

    auto issue = [&](int s) {
        uint32_t off = (uint32_t)(s % 3) * GSTG;
        uint32_t sa = sbase + (off + tid*GST) * 4;
        uint32_t sb = sbase + (off + 128*GST + tid*GST) * 4;
        const uint32_t* ga = Ag + s*16;
        const uint32_t* gb = Bg + s*16;
#pragma unroll
        for (int p = 0; p < 4; p++) {
            cp16(sa + p*16, ga + 4*p);
            cp16(sb + p*16, gb + 4*p);
        }
    };

    float acc[4][8][4];
#pragma unroll
    for (int t = 0; t < 4; t++)
#pragma unroll
        for (int j = 0; j < 8; j++)
#pragma unroll
            for (int r = 0; r < 4; r++) acc[t][j][r] = 0.f;

    // ldmatrix per-lane address components
    const int a_row = (lane & 7) + ((lane >> 3) & 1) * 8;  // + wm + 16t
    const int a_kw  = (lane >> 4) * 4;                     // + kk
    const int b_row = (lane & 7) + (lane >> 4) * 8;        // + wn + 16jj
    const int b_kw  = ((lane >> 3) & 1) * 4;               // + kk

    issue(0); CP_COMMIT();
    issue(1); CP_COMMIT();

    for (int s = 0; s < EMBED/16; s++) {
        cp_wait<1>(); __syncthreads();
        if (s + 2 < EMBED/16) issue(s + 2);
        CP_COMMIT();

        uint32_t offA = sbase + ((uint32_t)(s % 3) * GSTG) * 4;
        uint32_t offB = offA + (128*GST) * 4;

#pragma unroll
        for (int kk = 0; kk < 16; kk += 8) {
            uint32_t af[4][4], bf[8][2];
#pragma unroll
            for (int t = 0; t < 4; t++)
                ldsm4(af[t], offA + (uint32_t)((wm + 16*t + a_row)*GST + kk + a_kw) * 4);
#pragma unroll
            for (int jj = 0; jj < 4; jj++) {
                uint32_t r[4];
                ldsm4(r, offB + (uint32_t)((wn + 16*jj + b_row)*GST + kk + b_kw) * 4);
                bf[2*jj][0] = r[0]; bf[2*jj][1] = r[1];
                bf[2*jj+1][0] = r[2]; bf[2*jj+1][1] = r[3];
            }
#pragma unroll
            for (int t = 0; t < 4; t++)
#pragma unroll
                for (int j = 0; j < 8; j++)
                    mma_tf32(acc[t][j], af[t], bf[j]);
        }
    }

    // epilogue
#pragma unroll
    for (int j = 0; j < 8; j++) {
        int col = n0 + wn + 8*j + 2*c;
        float bv0 = bias[col], bv1 = bias[col + 1];
#pragma unroll
        for (int t = 0; t < 4; t++) {
            int row0 = m0 + wm + 16*t + g;
            float v00 = acc[t][j][0] + bv0, v01 = acc[t][j][1] + bv1;
            float v10 = acc[t][j][2] + bv0, v11 = acc[t][j][3] + bv1;
            if (TF32OUT) {
                uint32_t* Cu = (uint32_t*)Cv;
                uint2 u0; u0.x = f2tf(v00); u0.y = f2tf(v01);
                uint2 u1; u1.x = f2tf(v10); u1.y = f2tf(v11);
                *(uint2*)(Cu + (size_t)row0*EMBED + col)     = u0;
                *(uint2*)(Cu + (size_t)(row0+8)*EMBED + col) = u1;
            } else {
                float* Cf = (float*)Cv;
                *(float2*)(Cf + (size_t)row0*EMBED + col)     = make_float2(v00, v01);
                *(float2*)(Cf + (size_t)(row0+8)*EMBED + col) = make_float2(v10, v11);
            }
        }
    }
}

// ---------------- flash attention, tf32 mma, cp.async pipelined ----------------
// 128 q/CTA, 8 warps (16 q each), key tiles of 64, 3-stage K/V pipeline.
// smem (words): K 3x[64][68], V 3x[64][72], Q[128][68] aliased with P[64][136]
#define K_ST 68
#define V_ST 72
#define P_ST 136
#define KOFF(s) ((uint32_t)(s)*64*K_ST)
#define VBASE   (3*64*K_ST)
#define VOFF(s) (VBASE + (uint32_t)(s)*64*V_ST)
#define QPOFF   (VBASE + 3*64*V_ST)
#define ATTN_SMEM_WORDS (QPOFF + 64*P_ST)

__global__ __launch_bounds__(256)
void attn_tc(const uint32_t* __restrict__ Qg, const uint32_t* __restrict__ Kg,
             const uint32_t* __restrict__ Vg, uint32_t* __restrict__ Og) {
    extern __shared__ uint32_t sma[];
    const uint32_t sbase = (uint32_t)__cvta_generic_to_shared(sma);

    const int qt = blockIdx.x, h = blockIdx.y, nb = blockIdx.z;
    const int tid = threadIdx.x, warp = tid >> 5, lane = tid & 31;
    const int g = lane >> 2, c = lane & 3;
    const int q0 = warp * 16;
    const int base_q = nb*SEQ + qt*128;
    const int col0 = h * HDIM;

    auto kvissue = [&](int kt) {
        int s = kt % 3;
        int base_k = nb*SEQ + kt*64;
#pragma unroll
        for (int p = 0; p < 4; p++) {
            int idx = tid + 256*p;
            int row = idx >> 4, cp = (idx & 15) * 4;
            cp16(sbase + (KOFF(s) + row*K_ST + cp)*4, Kg + (size_t)(base_k+row)*EMBED + col0 + cp);
            cp16(sbase + (VOFF(s) + row*V_ST + cp)*4, Vg + (size_t)(base_k+row)*EMBED + col0 + cp);
        }
    };

    // Q tile load (group 0)
#pragma unroll
    for (int p = 0; p < 8; p++) {
        int idx = tid + 256*p;
        int row = idx >> 4, cp = (idx & 15) * 4;
        cp16(sbase + (QPOFF + row*K_ST + cp)*4, Qg + (size_t)(base_q+row)*EMBED + col0 + cp);
    }
    CP_COMMIT();
    kvissue(0); CP_COMMIT();
    kvissue(1); CP_COMMIT();

    cp_wait<2>(); __syncthreads();   // Q ready

    // Q fragments -> registers, scaled by 1/sqrt(64) (exact pow2 -> stays tf32)
    const int a_row = (lane & 7) + ((lane >> 3) & 1) * 8;
    const int a_kw  = (lane >> 4) * 4;
    const int b_row = (lane & 7) + (lane >> 4) * 8;
    const int b_kw  = ((lane >> 3) & 1) * 4;

    uint32_t qf[8][4];
#pragma unroll
    for (int ks = 0; ks < 8; ks++) {
        ldsm4(qf[ks], sbase + (QPOFF + (uint32_t)(q0 + a_row)*K_ST + 8*ks + a_kw)*4);
#pragma unroll
        for (int r = 0; r < 4; r++)
            qf[ks][r] = __float_as_uint(__uint_as_float(qf[ks][r]) * 0.125f);
    }

    float of[8][4];
#pragma unroll
    for (int j = 0; j < 8; j++)
#pragma unroll
        for (int r = 0; r < 4; r++) of[j][r] = 0.f;
    float m_lo = -1e30f, m_hi = -1e30f, l_lo = 0.f, l_hi = 0.f;

    for (int kt = 0; kt < SEQ/64; kt++) {
        cp_wait<1>(); __syncthreads();   // K/V tile kt ready; all warps past previous PV + qf reads
        if (kt + 2 < SEQ/64) kvissue(kt + 2);
        CP_COMMIT();
        const uint32_t Ko = KOFF(kt % 3);
        const uint32_t Vo = VOFF(kt % 3);

        // ---- S = Q @ K^T ----
        float sf[8][4];
#pragma unroll
        for (int j = 0; j < 8; j++)
#pragma unroll
            for (int r = 0; r < 4; r++) sf[j][r] = 0.f;
#pragma unroll
        for (int ks = 0; ks < 8; ks++) {
            uint32_t bf[8][2];
#pragma unroll
            for (int jj = 0; jj < 4; jj++) {
                uint32_t r[4];
                ldsm4(r, sbase + (Ko + (uint32_t)(16*jj + b_row)*K_ST + 8*ks + b_kw)*4);
                bf[2*jj][0] = r[0]; bf[2*jj][1] = r[1];
                bf[2*jj+1][0] = r[2]; bf[2*jj+1][1] = r[3];
            }
#pragma unroll
            for (int j = 0; j < 8; j++)
                mma_tf32(sf[j], qf[ks], bf[j]);
        }

        // ---- online softmax ----
        float mx_lo = -1e30f, mx_hi = -1e30f;
#pragma unroll
        for (int j = 0; j < 8; j++) {
            mx_lo = fmaxf(mx_lo, fmaxf(sf[j][0], sf[j][1]));
            mx_hi = fmaxf(mx_hi, fmaxf(sf[j][2], sf[j][3]));
        }
        mx_lo = fmaxf(mx_lo, __shfl_xor_sync(0xffffffffu, mx_lo, 1));
        mx_lo = fmaxf(mx_lo, __shfl_xor_sync(0xffffffffu, mx_lo, 2));
        mx_hi = fmaxf(mx_hi, __shfl_xor_sync(0xffffffffu, mx_hi, 1));
        mx_hi = fmaxf(mx_hi, __shfl_xor_sync(0xffffffffu, mx_hi, 2));

        float mn_lo = fmaxf(m_lo, mx_lo);
        float mn_hi = fmaxf(m_hi, mx_hi);
        float alpha_lo = __expf(m_lo - mn_lo);
        float alpha_hi = __expf(m_hi - mn_hi);

        float ps_lo = 0.f, ps_hi = 0.f;
#pragma unroll
        for (int j = 0; j < 8; j++) {
            sf[j][0] = __expf(sf[j][0] - mn_lo);
            sf[j][1] = __expf(sf[j][1] - mn_lo);
            sf[j][2] = __expf(sf[j][2] - mn_hi);
            sf[j][3] = __expf(sf[j][3] - mn_hi);
            ps_lo += sf[j][0] + sf[j][1];
            ps_hi += sf[j][2] + sf[j][3];
        }
        ps_lo += __shfl_xor_sync(0xffffffffu, ps_lo, 1);
        ps_lo += __shfl_xor_sync(0xffffffffu, ps_lo, 2);
        ps_hi += __shfl_xor_sync(0xffffffffu, ps_hi, 1);
        ps_hi += __shfl_xor_sync(0xffffffffu, ps_hi, 2);
        l_lo = l_lo * alpha_lo + ps_lo;
        l_hi = l_hi * alpha_hi + ps_hi;
        m_lo = mn_lo; m_hi = mn_hi;

        // ---- P store: [tok][q] stride 136, warp-local columns ----
#pragma unroll
        for (int j = 0; j < 8; j++) {
            sma[QPOFF + (8*j+2*c  )*P_ST + q0 + g]     = f2tf(sf[j][0]);
            sma[QPOFF + (8*j+2*c+1)*P_ST + q0 + g]     = f2tf(sf[j][1]);
            sma[QPOFF + (8*j+2*c  )*P_ST + q0 + g + 8] = f2tf(sf[j][2]);
            sma[QPOFF + (8*j+2*c+1)*P_ST + q0 + g + 8] = f2tf(sf[j][3]);
        }
        __syncwarp();

        // ---- O = O*alpha + P @ V ----
#pragma unroll
        for (int j = 0; j < 8; j++) {
            of[j][0] *= alpha_lo; of[j][1] *= alpha_lo;
            of[j][2] *= alpha_hi; of[j][3] *= alpha_hi;
        }
#pragma unroll
        for (int ks = 0; ks < 8; ks++) {
            uint32_t pa[4];
            pa[0] = sma[QPOFF + (8*ks+c  )*P_ST + q0 + g];
            pa[1] = sma[QPOFF + (8*ks+c  )*P_ST + q0 + g + 8];
            pa[2] = sma[QPOFF + (8*ks+c+4)*P_ST + q0 + g];
            pa[3] = sma[QPOFF + (8*ks+c+4)*P_ST + q0 + g + 8];
#pragma unroll
            for (int dj = 0; dj < 8; dj++) {
                uint32_t vb[2];
                vb[0] = sma[Vo + (8*ks+c  )*V_ST + 8*dj + g];
                vb[1] = sma[Vo + (8*ks+c+4)*V_ST + 8*dj + g];
                mma_tf32(of[dj], pa, vb);
            }
        }
    }

    // ---- epilogue: write tf32 bits (consumed by o-proj GEMM) ----
    float il_lo = 1.f / l_lo, il_hi = 1.f / l_hi;
#pragma unroll
    for (int dj = 0; dj < 8; dj++) {
        int col = col0 + 8*dj + 2*c;
        uint2 u0; u0.x = f2tf(of[dj][0]*il_lo); u0.y = f2tf(of[dj][1]*il_lo);
        uint2 u1; u1.x = f2tf(of[dj][2]*il_hi); u1.y = f2tf(of[dj][3]*il_hi);
        *(uint2*)(Og + (size_t)(base_q + q0 + g    )*EMBED + col) = u0;
        *(uint2*)(Og + (size_t)(base_q + q0 + g + 8)*EMBED + col) = u1;
    }
}

// ---------------- launch ----------------
extern "C" void kernel_launch(void* const* d_in, const int* in_sizes, int n_in,
                              void* d_out, int out_size) {
    const float* x  = (const float*)d_in[0];
    const float* Wq = (const float*)d_in[1];
    const float* bq = (const float*)d_in[2];
    const float* Aq = (const float*)d_in[3];
    const float* Bq = (const float*)d_in[4];
    const float* Wk = (const float*)d_in[5];
    const float* bk = (const float*)d_in[6];
    const float* Ak = (const float*)d_in[7];
    const float* Bk = (const float*)d_in[8];
    const float* Wv = (const float*)d_in[9];
    const float* bv = (const float*)d_in[10];
    const float* Av = (const float*)d_in[11];
    const float* Bv = (const float*)d_in[12];
    const float* Wo = (const float*)d_in[13];
    const float* bo = (const float*)d_in[14];
    const float* Ao = (const float*)d_in[15];
    const float* Bo = (const float*)d_in[16];
    float* out = (float*)d_out;

    uint32_t *Weff, *xt, *Q, *K, *V, *attn;
    cudaGetSymbolAddress((void**)&Weff, g_Weff);
    cudaGetSymbolAddress((void**)&xt, g_xt);
    cudaGetSymbolAddress((void**)&Q, g_Q);
    cudaGetSymbolAddress((void**)&K, g_K);
    cudaGetSymbolAddress((void**)&V, g_V);
    cudaGetSymbolAddress((void**)&attn, g_attn);

    // 0) x -> tf32
    xconv<<<TOKENS*EMBED/4/256, 256>>>((const float4*)x, (uint4*)xt);

    // 1) fold LoRA into effective tf32 weights
    dim3 fgrid(EMBED*EMBED/256, 4);
    fold4_kernel<<<fgrid, 256>>>(Wq, Aq, Bq, Wk, Ak, Bk, Wv, Av, Bv, Wo, Ao, Bo);

    // 2) fused Q/K/V projections
    size_t gsmem = (size_t)3 * GSTG * sizeof(uint32_t);   // 61440 B
    cudaFuncSetAttribute(gemm_tc<true>,  cudaFuncAttributeMaxDynamicSharedMemorySize, (int)gsmem);
    cudaFuncSetAttribute(gemm_tc<false>, cudaFuncAttributeMaxDynamicSharedMemorySize, (int)gsmem);
    dim3 qkv_grid(EMBED/128, TOKENS/128, 3);
    gemm_tc<true><<<qkv_grid, 128, gsmem>>>(xt, Weff, bq, bk, bv, Q, K, V);

    // 3) attention
    size_t asmem = (size_t)ATTN_SMEM_WORDS * sizeof(uint32_t);  // 142336 B
    cudaFuncSetAttribute(attn_tc, cudaFuncAttributeMaxDynamicSharedMemorySize, (int)asmem);
    dim3 agrid(SEQ/128, HEADS, NBATCH);
    attn_tc<<<agrid, 256, asmem>>>(Q, K, V, attn);

    // 4) output projection (fp32 out + bias)
    dim3 ogrid(EMBED/128, TOKENS/128, 1);
    gemm_tc<false><<<ogrid, 128, gsmem>>>(attn, Weff + 3*(size_t)(EMBED*EMBED), bo, bo, bo, out, out, out);
}

// round 5
// speedup vs baseline: 7.2386x; 1.0531x over previous
#include <cuda_runtime.h>
#include <math.h>
#include <stdint.h>

#define EMBED   1024
#define RANK    8
#define HEADS   16
#define HDIM    64
#define NBATCH  2
#define SEQ     2048
#define TOKENS  (NBATCH*SEQ)
#define LORA_SCALE 2.0f

// ---------------- scratch (tf32 bit patterns stored as uint32) ----------------
__device__ uint32_t g_Weff[4][EMBED*EMBED];
__device__ uint32_t g_xt[TOKENS*EMBED];
__device__ uint32_t g_Q[TOKENS*EMBED];
__device__ uint32_t g_K[TOKENS*EMBED];
__device__ uint32_t g_Vt[EMBED*TOKENS];   // V transposed: [embed_dim][token]
__device__ uint32_t g_attn[TOKENS*EMBED];

// ---------------- helpers ----------------
__device__ __forceinline__ uint32_t f2tf(float f) {
    uint32_t u; asm("cvt.rna.tf32.f32 %0, %1;" : "=r"(u) : "f"(f)); return u;
}
__device__ __forceinline__ void mma_tf32(float c[4], const uint32_t a[4], const uint32_t b[2]) {
    asm volatile("mma.sync.aligned.m16n8k8.row.col.f32.tf32.tf32.f32 "
        "{%0,%1,%2,%3}, {%4,%5,%6,%7}, {%8,%9}, {%0,%1,%2,%3};"
        : "+f"(c[0]), "+f"(c[1]), "+f"(c[2]), "+f"(c[3])
        : "r"(a[0]), "r"(a[1]), "r"(a[2]), "r"(a[3]), "r"(b[0]), "r"(b[1]));
}
__device__ __forceinline__ void ldsm4(uint32_t r[4], uint32_t addr) {
    asm volatile("ldmatrix.sync.aligned.m8n8.x4.shared.b16 {%0,%1,%2,%3}, [%4];"
        : "=r"(r[0]), "=r"(r[1]), "=r"(r[2]), "=r"(r[3]) : "r"(addr));
}
__device__ __forceinline__ void cp16(uint32_t saddr, const void* gaddr) {
    asm volatile("cp.async.cg.shared.global [%0], [%1], 16;" :: "r"(saddr), "l"(gaddr));
}
#define CP_COMMIT() asm volatile("cp.async.commit_group;")
template<int N> __device__ __forceinline__ void cp_wait() {
    asm volatile("cp.async.wait_group %0;" :: "n"(N));
}

// ---------------- xconv: fp32 -> tf32 bits ----------------
__global__ void xconv(const float4* __restrict__ in, uint4* __restrict__ out) {
    int i = blockIdx.x * blockDim.x + threadIdx.x;
    float4 v = in[i];
    uint4 u; u.x = f2tf(v.x); u.y = f2tf(v.y); u.z = f2tf(v.z); u.w = f2tf(v.w);
    out[i] = u;
}

// ---------------- fold: Weff[z] = tf32(W + 2 * B @ A) ----------------
__global__ void fold4_kernel(const float* __restrict__ W0, const float* __restrict__ A0, const float* __restrict__ B0,
                             const float* __restrict__ W1, const float* __restrict__ A1, const float* __restrict__ B1,
                             const float* __restrict__ W2, const float* __restrict__ A2, const float* __restrict__ B2,
                             const float* __restrict__ W3, const float* __restrict__ A3, const float* __restrict__ B3) {
    int z = blockIdx.y;
    const float *W, *A, *B;
    if (z == 0) { W = W0; A = A0; B = B0; }
    else if (z == 1) { W = W1; A = A1; B = B1; }
    else if (z == 2) { W = W2; A = A2; B = B2; }
    else { W = W3; A = A3; B = B3; }
    uint32_t* out = g_Weff[z];
    int idx = blockIdx.x * blockDim.x + threadIdx.x;
    int o = idx >> 10;
    int i = idx & (EMBED - 1);
    float s = 0.f;
#pragma unroll
    for (int r = 0; r < RANK; r++)
        s = fmaf(B[o*RANK + r], A[r*EMBED + i], s);
    out[idx] = f2tf(W[idx] + LORA_SCALE * s);
}

// ---------------- tf32 GEMM: C[M,N] = A[M,K] @ Bw[N,K]^T + bias ----------------
// CTA 128x128, 128 threads, warp tile 64x64, 3-stage cp.async, ldmatrix frags.
// MODE 0: z selects Q (row-major tf32), K (row-major tf32), V (TRANSPOSED tf32 -> Vt)
// MODE 1: fp32 row-major + bias (output projection)
#define GST 20
#define GSTG (2*128*GST)    // 5120 words per stage
template<int MODE>
__global__ __launch_bounds__(128)
void gemm_tc(const uint32_t* __restrict__ A, const uint32_t* __restrict__ Wbase,
             const float* __restrict__ bz0, const float* __restrict__ bz1, const float* __restrict__ bz2,
             uint32_t* __restrict__ oq, uint32_t* __restrict__ okk, uint32_t* __restrict__ ovt,
             float* __restrict__ ofp) {
    extern __shared__ uint32_t smg[];
    const int z = (MODE == 0) ? blockIdx.z : 0;
    const uint32_t* Bw = Wbase + (size_t)z * (EMBED*EMBED);
    const float* bias = (z == 0) ? bz0 : (z == 1) ? bz1 : bz2;

    const int tid = threadIdx.x, warp = tid >> 5, lane = tid & 31;
    const int g = lane >> 2, c = lane & 3;
    const int wm = (warp & 1) * 64, wn = (warp >> 1) * 64;
    const int m0 = blockIdx.y * 128, n0 = blockIdx.x * 128;

    const uint32_t sbase = (uint32_t)__cvta_generic_to_shared(smg);
    const uint32_t* Ag = A  + (size_t)(m0 + tid) * EMBED;
    const uint32_t* Bg = Bw + (size_t)(n0 + tid) * EMBED;

    auto issue = [&](int s) {
        uint32_t off = (uint32_t)(s % 3) * GSTG;
        uint32_t sa = sbase + (off + tid*GST) * 4;
        uint32_t sb = sbase + (off + 128*GST + tid*GST) * 4;
        const uint32_t* ga = Ag + s*16;
        const uint32_t* gb = Bg + s*16;
#pragma unroll
        for (int p = 0; p < 4; p++) {
            cp16(sa + p*16, ga + 4*p);
            cp16(sb + p*16, gb + 4*p);
        }
    };

    float acc[4][8][4];
#pragma unroll
    for (int t = 0; t < 4; t++)
#pragma unroll
        for (int j = 0; j < 8; j++)
#pragma unroll
            for (int r = 0; r < 4; r++) acc[t][j][r] = 0.f;

    const int a_row = (lane & 7) + ((lane >> 3) & 1) * 8;
    const int a_kw  = (lane >> 4) * 4;
    const int b_row = (lane & 7) + (lane >> 4) * 8;
    const int b_kw  = ((lane >> 3) & 1) * 4;

    issue(0); CP_COMMIT();
    issue(1); CP_COMMIT();

    for (int s = 0; s < EMBED/16; s++) {
        cp_wait<1>(); __syncthreads();
        if (s + 2 < EMBED/16) issue(s + 2);
        CP_COMMIT();

        uint32_t offA = sbase + ((uint32_t)(s % 3) * GSTG) * 4;
        uint32_t offB = offA + (128*GST) * 4;

#pragma unroll
        for (int kk = 0; kk < 16; kk += 8) {
            uint32_t af[4][4], bf[8][2];
#pragma unroll
            for (int t = 0; t < 4; t++)
                ldsm4(af[t], offA + (uint32_t)((wm + 16*t + a_row)*GST + kk + a_kw) * 4);
#pragma unroll
            for (int jj = 0; jj < 4; jj++) {
                uint32_t r[4];
                ldsm4(r, offB + (uint32_t)((wn + 16*jj + b_row)*GST + kk + b_kw) * 4);
                bf[2*jj][0] = r[0]; bf[2*jj][1] = r[1];
                bf[2*jj+1][0] = r[2]; bf[2*jj+1][1] = r[3];
            }
#pragma unroll
            for (int t = 0; t < 4; t++)
#pragma unroll
                for (int j = 0; j < 8; j++)
                    mma_tf32(acc[t][j], af[t], bf[j]);
        }
    }

    // epilogue
#pragma unroll
    for (int j = 0; j < 8; j++) {
        int col = n0 + wn + 8*j + 2*c;
        float bv0 = bias[col], bv1 = bias[col + 1];
#pragma unroll
        for (int t = 0; t < 4; t++) {
            int row0 = m0 + wm + 16*t + g;
            float v00 = acc[t][j][0] + bv0, v01 = acc[t][j][1] + bv1;
            float v10 = acc[t][j][2] + bv0, v11 = acc[t][j][3] + bv1;
            if (MODE == 1) {
                *(float2*)(ofp + (size_t)row0*EMBED + col)     = make_float2(v00, v01);
                *(float2*)(ofp + (size_t)(row0+8)*EMBED + col) = make_float2(v10, v11);
            } else if (z == 2) {
                // V transposed: Vt[col][row]
                ovt[(size_t)col*TOKENS + row0]         = f2tf(v00);
                ovt[(size_t)col*TOKENS + row0 + 8]     = f2tf(v10);
                ovt[(size_t)(col+1)*TOKENS + row0]     = f2tf(v01);
                ovt[(size_t)(col+1)*TOKENS + row0 + 8] = f2tf(v11);
            } else {
                uint32_t* Cu = (z == 0) ? oq : okk;
                uint2 u0; u0.x = f2tf(v00); u0.y = f2tf(v01);
                uint2 u1; u1.x = f2tf(v10); u1.y = f2tf(v11);
                *(uint2*)(Cu + (size_t)row0*EMBED + col)     = u0;
                *(uint2*)(Cu + (size_t)(row0+8)*EMBED + col) = u1;
            }
        }
    }
}

// ---------------- flash attention, tf32 mma, 2-stage cp.async, ldmatrix V ----------------
// 128 q/CTA, 8 warps (16 q each), key tiles of 64, V^T gmem layout.
// smem (words): K 2x[64][68], Vt 2x[64][68], QP = Q[128][68] aliased with P[64][136]
#define K_ST 68
#define P_ST 136
#define KO(s)  ((uint32_t)(s)*64*K_ST)
#define VO(s)  (2*64*K_ST + (uint32_t)(s)*64*K_ST)
#define QPOFF  (4*64*K_ST)
#define ATTN_SMEM_WORDS (QPOFF + 128*K_ST)     // 26112 words = 104448 B

__global__ __launch_bounds__(256, 2)
void attn_tc(const uint32_t* __restrict__ Qg, const uint32_t* __restrict__ Kg,
             const uint32_t* __restrict__ Vt, uint32_t* __restrict__ Og) {
    extern __shared__ uint32_t sma[];
    const uint32_t sbase = (uint32_t)__cvta_generic_to_shared(sma);

    const int qt = blockIdx.x, h = blockIdx.y, nb = blockIdx.z;
    const int tid = threadIdx.x, warp = tid >> 5, lane = tid & 31;
    const int g = lane >> 2, c = lane & 3;
    const int q0 = warp * 16;
    const int base_q = nb*SEQ + qt*128;
    const int col0 = h * HDIM;

    auto kvissue = [&](int kt) {
        int s = kt & 1;
        int base_k = nb*SEQ + kt*64;
#pragma unroll
        for (int p = 0; p < 4; p++) {
            int idx = tid + 256*p;
            int row = idx >> 4, q = idx & 15;
            cp16(sbase + (KO(s) + row*K_ST)*4 + q*16,
                 Kg + (size_t)(base_k + row)*EMBED + col0 + 4*q);
            cp16(sbase + (VO(s) + row*K_ST)*4 + q*16,
                 Vt + (size_t)(col0 + row)*TOKENS + base_k + 4*q);
        }
    };

    // Q tile load (group 0)
#pragma unroll
    for (int p = 0; p < 8; p++) {
        int idx = tid + 256*p;
        int row = idx >> 4, q = idx & 15;
        cp16(sbase + (QPOFF + row*K_ST)*4 + q*16,
             Qg + (size_t)(base_q + row)*EMBED + col0 + 4*q);
    }
    CP_COMMIT();
    kvissue(0); CP_COMMIT();
    kvissue(1); CP_COMMIT();

    cp_wait<2>(); __syncthreads();   // Q ready

    const int a_row = (lane & 7) + ((lane >> 3) & 1) * 8;
    const int a_kw  = (lane >> 4) * 4;
    const int b_row = (lane & 7) + (lane >> 4) * 8;
    const int b_kw  = ((lane >> 3) & 1) * 4;

    uint32_t qf[8][4];
#pragma unroll
    for (int ks = 0; ks < 8; ks++) {
        ldsm4(qf[ks], sbase + (QPOFF + (uint32_t)(q0 + a_row)*K_ST + 8*ks + a_kw)*4);
#pragma unroll
        for (int r = 0; r < 4; r++)
            qf[ks][r] = __float_as_uint(__uint_as_float(qf[ks][r]) * 0.125f);
    }
    __syncthreads();   // everyone's Q frags extracted before P overwrites region

    float of[8][4];
#pragma unroll
    for (int j = 0; j < 8; j++)
#pragma unroll
        for (int r = 0; r < 4; r++) of[j][r] = 0.f;
    float m_lo = -1e30f, m_hi = -1e30f, l_lo = 0.f, l_hi = 0.f;

    for (int kt = 0; kt < SEQ/64; kt++) {
        cp_wait<1>(); __syncthreads();   // tile kt ready (kt+1 in flight)
        const uint32_t Ko = KO(kt & 1);
        const uint32_t Vo = VO(kt & 1);

        // ---- S = Q @ K^T ----
        float sf[8][4];
#pragma unroll
        for (int j = 0; j < 8; j++)
#pragma unroll
            for (int r = 0; r < 4; r++) sf[j][r] = 0.f;
#pragma unroll
        for (int ks = 0; ks < 8; ks++) {
            uint32_t bf[8][2];
#pragma unroll
            for (int jj = 0; jj < 4; jj++) {
                uint32_t r[4];
                ldsm4(r, sbase + (Ko + (uint32_t)(16*jj + b_row)*K_ST + 8*ks + b_kw)*4);
                bf[2*jj][0] = r[0]; bf[2*jj][1] = r[1];
                bf[2*jj+1][0] = r[2]; bf[2*jj+1][1] = r[3];
            }
#pragma unroll
            for (int j = 0; j < 8; j++)
                mma_tf32(sf[j], qf[ks], bf[j]);
        }

        // ---- online softmax ----
        float mx_lo = -1e30f, mx_hi = -1e30f;
#pragma unroll
        for (int j = 0; j < 8; j++) {
            mx_lo = fmaxf(mx_lo, fmaxf(sf[j][0], sf[j][1]));
            mx_hi = fmaxf(mx_hi, fmaxf(sf[j][2], sf[j][3]));
        }
        mx_lo = fmaxf(mx_lo, __shfl_xor_sync(0xffffffffu, mx_lo, 1));
        mx_lo = fmaxf(mx_lo, __shfl_xor_sync(0xffffffffu, mx_lo, 2));
        mx_hi = fmaxf(mx_hi, __shfl_xor_sync(0xffffffffu, mx_hi, 1));
        mx_hi = fmaxf(mx_hi, __shfl_xor_sync(0xffffffffu, mx_hi, 2));

        float mn_lo = fmaxf(m_lo, mx_lo);
        float mn_hi = fmaxf(m_hi, mx_hi);
        float alpha_lo = __expf(m_lo - mn_lo);
        float alpha_hi = __expf(m_hi - mn_hi);

        float ps_lo = 0.f, ps_hi = 0.f;
#pragma unroll
        for (int j = 0; j < 8; j++) {
            sf[j][0] = __expf(sf[j][0] - mn_lo);
            sf[j][1] = __expf(sf[j][1] - mn_lo);
            sf[j][2] = __expf(sf[j][2] - mn_hi);
            sf[j][3] = __expf(sf[j][3] - mn_hi);
            ps_lo += sf[j][0] + sf[j][1];
            ps_hi += sf[j][2] + sf[j][3];
        }
        ps_lo += __shfl_xor_sync(0xffffffffu, ps_lo, 1);
        ps_lo += __shfl_xor_sync(0xffffffffu, ps_lo, 2);
        ps_hi += __shfl_xor_sync(0xffffffffu, ps_hi, 1);
        ps_hi += __shfl_xor_sync(0xffffffffu, ps_hi, 2);
        l_lo = l_lo * alpha_lo + ps_lo;
        l_hi = l_hi * alpha_hi + ps_hi;
        m_lo = mn_lo; m_hi = mn_hi;

        // ---- P store: [tok][q] stride 136, warp-local columns ----
#pragma unroll
        for (int j = 0; j < 8; j++) {
            sma[QPOFF + (8*j+2*c  )*P_ST + q0 + g]     = f2tf(sf[j][0]);
            sma[QPOFF + (8*j+2*c+1)*P_ST + q0 + g]     = f2tf(sf[j][1]);
            sma[QPOFF + (8*j+2*c  )*P_ST + q0 + g + 8] = f2tf(sf[j][2]);
            sma[QPOFF + (8*j+2*c+1)*P_ST + q0 + g + 8] = f2tf(sf[j][3]);
        }
        __syncwarp();

        // ---- O = O*alpha + P @ V  (V frags via ldmatrix from Vt[d][tok]) ----
#pragma unroll
        for (int j = 0; j < 8; j++) {
            of[j][0] *= alpha_lo; of[j][1] *= alpha_lo;
            of[j][2] *= alpha_hi; of[j][3] *= alpha_hi;
        }
#pragma unroll
        for (int ks = 0; ks < 8; ks++) {
            uint32_t pa[4];
            pa[0] = sma[QPOFF + (8*ks+c  )*P_ST + q0 + g];
            pa[1] = sma[QPOFF + (8*ks+c  )*P_ST + q0 + g + 8];
            pa[2] = sma[QPOFF + (8*ks+c+4)*P_ST + q0 + g];
            pa[3] = sma[QPOFF + (8*ks+c+4)*P_ST + q0 + g + 8];
            uint32_t vf[8][2];
#pragma unroll
            for (int jj = 0; jj < 4; jj++) {
                uint32_t r[4];
                ldsm4(r, sbase + (Vo + (uint32_t)(16*jj + b_row)*K_ST + 8*ks + b_kw)*4);
                vf[2*jj][0] = r[0]; vf[2*jj][1] = r[1];
                vf[2*jj+1][0] = r[2]; vf[2*jj+1][1] = r[3];
            }
#pragma unroll
            for (int dj = 0; dj < 8; dj++)
                mma_tf32(of[dj], pa, vf[dj]);
        }

        __syncthreads();                 // all warps done with K/Vt slot kt&1
        if (kt + 2 < SEQ/64) kvissue(kt + 2);
        CP_COMMIT();
    }

    // ---- epilogue: write tf32 bits (consumed by o-proj GEMM) ----
    float il_lo = 1.f / l_lo, il_hi = 1.f / l_hi;
#pragma unroll
    for (int dj = 0; dj < 8; dj++) {
        int col = col0 + 8*dj + 2*c;
        uint2 u0; u0.x = f2tf(of[dj][0]*il_lo); u0.y = f2tf(of[dj][1]*il_lo);
        uint2 u1; u1.x = f2tf(of[dj][2]*il_hi); u1.y = f2tf(of[dj][3]*il_hi);
        *(uint2*)(Og + (size_t)(base_q + q0 + g    )*EMBED + col) = u0;
        *(uint2*)(Og + (size_t)(base_q + q0 + g + 8)*EMBED + col) = u1;
    }
}

// ---------------- launch ----------------
extern "C" void kernel_launch(void* const* d_in, const int* in_sizes, int n_in,
                              void* d_out, int out_size) {
    const float* x  = (const float*)d_in[0];
    const float* Wq = (const float*)d_in[1];
    const float* bq = (const float*)d_in[2];
    const float* Aq = (const float*)d_in[3];
    const float* Bq = (const float*)d_in[4];
    const float* Wk = (const float*)d_in[5];
    const float* bk = (const float*)d_in[6];
    const float* Ak = (const float*)d_in[7];
    const float* Bk = (const float*)d_in[8];
    const float* Wv = (const float*)d_in[9];
    const float* bv = (const float*)d_in[10];
    const float* Av = (const float*)d_in[11];
    const float* Bv = (const float*)d_in[12];
    const float* Wo = (const float*)d_in[13];
    const float* bo = (const float*)d_in[14];
    const float* Ao = (const float*)d_in[15];
    const float* Bo = (const float*)d_in[16];
    float* out = (float*)d_out;

    uint32_t *Weff, *xt, *Q, *K, *Vt, *attn;
    cudaGetSymbolAddress((void**)&Weff, g_Weff);
    cudaGetSymbolAddress((void**)&xt, g_xt);
    cudaGetSymbolAddress((void**)&Q, g_Q);
    cudaGetSymbolAddress((void**)&K, g_K);
    cudaGetSymbolAddress((void**)&Vt, g_Vt);
    cudaGetSymbolAddress((void**)&attn, g_attn);

    // 0) x -> tf32
    xconv<<<TOKENS*EMBED/4/256, 256>>>((const float4*)x, (uint4*)xt);

    // 1) fold LoRA into effective tf32 weights
    dim3 fgrid(EMBED*EMBED/256, 4);
    fold4_kernel<<<fgrid, 256>>>(Wq, Aq, Bq, Wk, Ak, Bk, Wv, Av, Bv, Wo, Ao, Bo);

    // 2) fused Q/K/V projections (V emitted transposed)
    size_t gsmem = (size_t)3 * GSTG * sizeof(uint32_t);   // 61440 B
    cudaFuncSetAttribute(gemm_tc<0>, cudaFuncAttributeMaxDynamicSharedMemorySize, (int)gsmem);
    cudaFuncSetAttribute(gemm_tc<1>, cudaFuncAttributeMaxDynamicSharedMemorySize, (int)gsmem);
    dim3 qkv_grid(EMBED/128, TOKENS/128, 3);
    gemm_tc<0><<<qkv_grid, 128, gsmem>>>(xt, Weff, bq, bk, bv, Q, K, Vt, nullptr);

    // 3) attention (2 CTAs/SM)
    size_t asmem = (size_t)ATTN_SMEM_WORDS * sizeof(uint32_t);   // 104448 B
    cudaFuncSetAttribute(attn_tc, cudaFuncAttributeMaxDynamicSharedMemorySize, (int)asmem);
    dim3 agrid(SEQ/128, HEADS, NBATCH);
    attn_tc<<<agrid, 256, asmem>>>(Q, K, Vt, attn);

    // 4) output projection (fp32 out + bias)
    dim3 ogrid(EMBED/128, TOKENS/128, 1);
    gemm_tc<1><<<ogrid, 128, gsmem>>>(attn, Weff + 3*(size_t)(EMBED*EMBED), bo, bo, bo,
                                      nullptr, nullptr, nullptr, out);
}

// round 6
// speedup vs baseline: 13.0150x; 1.7980x over previous
#include <cuda_runtime.h>
#include <cuda_fp16.h>
#include <math.h>
#include <stdint.h>

#define EMBED   1024
#define RANK    8
#define HEADS   16
#define HDIM    64
#define NBATCH  2
#define SEQ     2048
#define TOKENS  (NBATCH*SEQ)
#define LORA_SCALE 2.0f

// ---------------- scratch (fp16 pairs stored as uint32) ----------------
__device__ uint32_t g_Weff[4][EMBED*EMBED/2];
__device__ uint32_t g_xt[TOKENS*EMBED/2];
__device__ uint32_t g_Q[TOKENS*EMBED/2];
__device__ uint32_t g_K[TOKENS*EMBED/2];
__device__ uint32_t g_V[TOKENS*EMBED/2];
__device__ uint32_t g_attn[TOKENS*EMBED/2];

// ---------------- helpers ----------------
__device__ __forceinline__ uint32_t pkh2(float a, float b) {
    __half2 h = __floats2half2_rn(a, b);
    return *(uint32_t*)&h;
}
__device__ __forceinline__ void mma_f16(float c[4], const uint32_t a[4], const uint32_t b[2]) {
    asm volatile("mma.sync.aligned.m16n8k16.row.col.f32.f16.f16.f32 "
        "{%0,%1,%2,%3}, {%4,%5,%6,%7}, {%8,%9}, {%0,%1,%2,%3};"
        : "+f"(c[0]), "+f"(c[1]), "+f"(c[2]), "+f"(c[3])
        : "r"(a[0]), "r"(a[1]), "r"(a[2]), "r"(a[3]), "r"(b[0]), "r"(b[1]));
}
__device__ __forceinline__ void ldsm4(uint32_t r[4], uint32_t addr) {
    asm volatile("ldmatrix.sync.aligned.m8n8.x4.shared.b16 {%0,%1,%2,%3}, [%4];"
        : "=r"(r[0]), "=r"(r[1]), "=r"(r[2]), "=r"(r[3]) : "r"(addr));
}
__device__ __forceinline__ void ldsm4t(uint32_t r[4], uint32_t addr) {
    asm volatile("ldmatrix.sync.aligned.m8n8.x4.trans.shared.b16 {%0,%1,%2,%3}, [%4];"
        : "=r"(r[0]), "=r"(r[1]), "=r"(r[2]), "=r"(r[3]) : "r"(addr));
}
__device__ __forceinline__ void cp16(uint32_t saddr, const void* gaddr) {
    asm volatile("cp.async.cg.shared.global [%0], [%1], 16;" :: "r"(saddr), "l"(gaddr));
}
#define CP_COMMIT() asm volatile("cp.async.commit_group;")
template<int N> __device__ __forceinline__ void cp_wait() {
    asm volatile("cp.async.wait_group %0;" :: "n"(N));
}

// ---------------- xconv: fp32 -> fp16 ----------------
__global__ void xconv(const float4* __restrict__ in, uint2* __restrict__ out) {
    int i = blockIdx.x * blockDim.x + threadIdx.x;
    float4 v = in[i];
    out[i] = make_uint2(pkh2(v.x, v.y), pkh2(v.z, v.w));
}

// ---------------- fold: Weff[z] = h(wscale * (W + 2 * B @ A)) ----------------
// z==0 (Q) additionally folds the attention 1/sqrt(64) = 0.125 scale.
__global__ void fold4_kernel(const float* __restrict__ W0, const float* __restrict__ A0, const float* __restrict__ B0,
                             const float* __restrict__ W1, const float* __restrict__ A1, const float* __restrict__ B1,
                             const float* __restrict__ W2, const float* __restrict__ A2, const float* __restrict__ B2,
                             const float* __restrict__ W3, const float* __restrict__ A3, const float* __restrict__ B3) {
    int z = blockIdx.y;
    const float *W, *A, *B;
    if (z == 0) { W = W0; A = A0; B = B0; }
    else if (z == 1) { W = W1; A = A1; B = B1; }
    else if (z == 2) { W = W2; A = A2; B = B2; }
    else { W = W3; A = A3; B = B3; }
    float wscale = (z == 0) ? 0.125f : 1.0f;
    uint32_t* out = g_Weff[z];
    int idx = blockIdx.x * blockDim.x + threadIdx.x;   // pair index
    int o = idx >> 9;
    int i = (idx & 511) * 2;
    float s0 = 0.f, s1 = 0.f;
#pragma unroll
    for (int r = 0; r < RANK; r++) {
        float br = B[o*RANK + r];
        s0 = fmaf(br, A[r*EMBED + i],   s0);
        s1 = fmaf(br, A[r*EMBED + i+1], s1);
    }
    out[idx] = pkh2(wscale * (W[o*EMBED + i]   + LORA_SCALE * s0),
                    wscale * (W[o*EMBED + i+1] + LORA_SCALE * s1));
}

// ---------------- fp16 GEMM: C[M,N] = A[M,K] @ Bw[N,K]^T + bias ----------------
// CTA 128x128, 128 threads, warp tile 64x64, 3-stage cp.async (k32/stage),
// smem row stride 80B (16*5, odd multiple -> ldmatrix conflict-free).
// MODE 0: fp16 out (+ bias, z-scaled), MODE 1: fp32 out (+ bias)
#define GSTAGE 20480   // bytes per stage (A 128*80 + B 128*80)
#define GEMM_SMEM (3*GSTAGE)
template<int MODE>
__global__ __launch_bounds__(128)
void gemm_tc(const __half* __restrict__ A, const __half* __restrict__ Wbase,
             const float* __restrict__ bz0, const float* __restrict__ bz1, const float* __restrict__ bz2,
             uint32_t* __restrict__ o0, uint32_t* __restrict__ o1, uint32_t* __restrict__ o2,
             float* __restrict__ ofp) {
    extern __shared__ char smg[];
    const int z = (MODE == 0) ? blockIdx.z : 0;
    const __half* Bw = Wbase + (size_t)z * (EMBED*EMBED);
    const float* bias = (z == 0) ? bz0 : (z == 1) ? bz1 : bz2;
    const float bscale = (MODE == 0 && z == 0) ? 0.125f : 1.0f;
    uint32_t* Ch = (z == 0) ? o0 : (z == 1) ? o1 : o2;

    const int tid = threadIdx.x, warp = tid >> 5, lane = tid & 31;
    const int g = lane >> 2, c = lane & 3;
    const int wm = (warp & 1) * 64, wn = (warp >> 1) * 64;
    const int m0 = blockIdx.y * 128, n0 = blockIdx.x * 128;

    const uint32_t sbase = (uint32_t)__cvta_generic_to_shared(smg);
    const __half* Ag = A  + (size_t)(m0 + tid) * EMBED;
    const __half* Bg = Bw + (size_t)(n0 + tid) * EMBED;

    auto issue = [&](int s) {
        uint32_t off = sbase + (uint32_t)(s % 3) * GSTAGE;
        const __half* ga = Ag + s*32;
        const __half* gb = Bg + s*32;
#pragma unroll
        for (int p = 0; p < 4; p++) {
            cp16(off + tid*80 + p*16,         ga + 8*p);
            cp16(off + 10240 + tid*80 + p*16, gb + 8*p);
        }
    };

    float acc[4][8][4];
#pragma unroll
    for (int t = 0; t < 4; t++)
#pragma unroll
        for (int j = 0; j < 8; j++)
#pragma unroll
            for (int r = 0; r < 4; r++) acc[t][j][r] = 0.f;

    const int a_row  = lane & 15;
    const int a_half = (lane >> 4) * 16;
    const int b_row  = (lane & 7) + ((lane >> 4) << 3);
    const int b_half = ((lane >> 3) & 1) * 16;

    issue(0); CP_COMMIT();
    issue(1); CP_COMMIT();

    for (int s = 0; s < EMBED/32; s++) {
        cp_wait<1>(); __syncthreads();
        if (s + 2 < EMBED/32) issue(s + 2);
        CP_COMMIT();

        uint32_t offA = sbase + (uint32_t)(s % 3) * GSTAGE;
        uint32_t offB = offA + 10240;

#pragma unroll
        for (int kk = 0; kk < 2; kk++) {
            uint32_t af[4][4], bf[8][2];
#pragma unroll
            for (int t = 0; t < 4; t++)
                ldsm4(af[t], offA + (uint32_t)(wm + 16*t + a_row)*80 + a_half + kk*32);
#pragma unroll
            for (int jj = 0; jj < 4; jj++) {
                uint32_t r[4];
                ldsm4(r, offB + (uint32_t)(wn + 16*jj + b_row)*80 + b_half + kk*32);
                bf[2*jj][0] = r[0]; bf[2*jj][1] = r[1];
                bf[2*jj+1][0] = r[2]; bf[2*jj+1][1] = r[3];
            }
#pragma unroll
            for (int t = 0; t < 4; t++)
#pragma unroll
                for (int j = 0; j < 8; j++)
                    mma_f16(acc[t][j], af[t], bf[j]);
        }
    }

    // epilogue
#pragma unroll
    for (int j = 0; j < 8; j++) {
        int col = n0 + wn + 8*j + 2*c;
        float bv0 = bias[col] * bscale, bv1 = bias[col + 1] * bscale;
#pragma unroll
        for (int t = 0; t < 4; t++) {
            int row0 = m0 + wm + 16*t + g;
            float v00 = acc[t][j][0] + bv0, v01 = acc[t][j][1] + bv1;
            float v10 = acc[t][j][2] + bv0, v11 = acc[t][j][3] + bv1;
            if (MODE == 1) {
                *(float2*)(ofp + (size_t)row0*EMBED + col)     = make_float2(v00, v01);
                *(float2*)(ofp + (size_t)(row0+8)*EMBED + col) = make_float2(v10, v11);
            } else {
                Ch[((size_t)row0*EMBED + col) >> 1]     = pkh2(v00, v01);
                Ch[((size_t)(row0+8)*EMBED + col) >> 1] = pkh2(v10, v11);
            }
        }
    }
}

// ---------------- flash attention, fp16 mma ----------------
// 128 q/CTA, 8 warps (16 q each), key tiles of 64, 2-stage K/V cp.async.
// smem bytes: K 2x[64 tok][72h], V 2x[64 tok][72h], QP region: Q[128][72h] alias P[64 q... P is [q][tok] [128?]
//   P: [128 q][136h]? no: P is per 64-tok tile: [q up to 128][tok 64] -> stored [q][tok] stride 136h for ldmatrix A.
// Strides: 144B rows (16*9) and 272B rows (16*17) -> conflict-free ldmatrix.
#define KOB(s)  ((uint32_t)(s)*9216u)
#define VOB(s)  (18432u + (uint32_t)(s)*9216u)
#define QPO     36864u
// Q region: 128*144 = 18432 B ; P region: 128 rows * 272 B = 34816 B > Q. Total smem:
#define ATTN_SMEM (36864 + 34816)   // 71680 B

__global__ __launch_bounds__(256, 2)
void attn_tc(const __half* __restrict__ Qg, const __half* __restrict__ Kg,
             const __half* __restrict__ Vg, uint32_t* __restrict__ Og) {
    extern __shared__ char sma[];
    const uint32_t sbase = (uint32_t)__cvta_generic_to_shared(sma);

    const int qt = blockIdx.x, h = blockIdx.y, nb = blockIdx.z;
    const int tid = threadIdx.x, warp = tid >> 5, lane = tid & 31;
    const int g = lane >> 2, c = lane & 3;
    const int q0 = warp * 16;
    const int base_q = nb*SEQ + qt*128;
    const int col0 = h * HDIM;

    auto kvissue = [&](int kt) {
        int s = kt & 1;
        int base_k = nb*SEQ + kt*64;
#pragma unroll
        for (int p = 0; p < 2; p++) {
            int idx = tid + 256*p;            // 0..511
            int row = idx >> 3, q = idx & 7;
            cp16(sbase + KOB(s) + row*144 + q*16,
                 Kg + (size_t)(base_k + row)*EMBED + col0 + 8*q);
        }
#pragma unroll
        for (int p = 0; p < 2; p++) {
            int idx = tid + 256*p;
            int row = idx >> 3, q = idx & 7;
            cp16(sbase + VOB(s) + row*144 + q*16,
                 Vg + (size_t)(base_k + row)*EMBED + col0 + 8*q);
        }
    };

    // Q tile (128 rows x 64 halves), stride 144B
#pragma unroll
    for (int p = 0; p < 4; p++) {
        int idx = tid + 256*p;                // 0..1023
        int row = idx >> 3, q = idx & 7;
        cp16(sbase + QPO + row*144 + q*16,
             Qg + (size_t)(base_q + row)*EMBED + col0 + 8*q);
    }
    CP_COMMIT();
    kvissue(0); CP_COMMIT();
    kvissue(1); CP_COMMIT();

    cp_wait<2>(); __syncthreads();   // Q ready

    const int b_row  = (lane & 7) + ((lane >> 4) << 3);     // non-trans B rows
    const int b_half = ((lane >> 3) & 1) * 16;
    const int v_row  = (lane & 7) + (((lane >> 3) & 1) << 3); // trans V rows
    const int v_half = (lane >> 4) * 16;

    // Q fragments (scale already folded into Weff_q)
    uint32_t qf[4][4];
#pragma unroll
    for (int kk = 0; kk < 4; kk++)
        ldsm4(qf[kk], sbase + QPO + (uint32_t)(q0 + (lane & 15))*144 + (lane >> 4)*16 + kk*32);
    __syncthreads();   // all Q frags extracted before P overwrites region

    float of[8][4];
#pragma unroll
    for (int j = 0; j < 8; j++)
#pragma unroll
        for (int r = 0; r < 4; r++) of[j][r] = 0.f;
    float m_lo = -1e30f, m_hi = -1e30f, l_lo = 0.f, l_hi = 0.f;

    for (int kt = 0; kt < SEQ/64; kt++) {
        cp_wait<1>(); __syncthreads();
        const uint32_t Ko = KOB(kt & 1);
        const uint32_t Vo = VOB(kt & 1);

        // ---- S = Q @ K^T  (A=Q 16x64, B=K[tok][d] non-trans) ----
        float sf[8][4];
#pragma unroll
        for (int j = 0; j < 8; j++)
#pragma unroll
            for (int r = 0; r < 4; r++) sf[j][r] = 0.f;
#pragma unroll
        for (int kk = 0; kk < 4; kk++) {   // d-chunks of 16
            uint32_t bf[8][2];
#pragma unroll
            for (int jj = 0; jj < 4; jj++) {
                uint32_t r[4];
                ldsm4(r, sbase + Ko + (uint32_t)(16*jj + b_row)*144 + b_half + kk*32);
                bf[2*jj][0] = r[0]; bf[2*jj][1] = r[1];
                bf[2*jj+1][0] = r[2]; bf[2*jj+1][1] = r[3];
            }
#pragma unroll
            for (int j = 0; j < 8; j++)
                mma_f16(sf[j], qf[kk], bf[j]);
        }

        // ---- online softmax ----
        float mx_lo = -1e30f, mx_hi = -1e30f;
#pragma unroll
        for (int j = 0; j < 8; j++) {
            mx_lo = fmaxf(mx_lo, fmaxf(sf[j][0], sf[j][1]));
            mx_hi = fmaxf(mx_hi, fmaxf(sf[j][2], sf[j][3]));
        }
        mx_lo = fmaxf(mx_lo, __shfl_xor_sync(0xffffffffu, mx_lo, 1));
        mx_lo = fmaxf(mx_lo, __shfl_xor_sync(0xffffffffu, mx_lo, 2));
        mx_hi = fmaxf(mx_hi, __shfl_xor_sync(0xffffffffu, mx_hi, 1));
        mx_hi = fmaxf(mx_hi, __shfl_xor_sync(0xffffffffu, mx_hi, 2));

        float mn_lo = fmaxf(m_lo, mx_lo);
        float mn_hi = fmaxf(m_hi, mx_hi);
        float alpha_lo = __expf(m_lo - mn_lo);
        float alpha_hi = __expf(m_hi - mn_hi);

        float ps_lo = 0.f, ps_hi = 0.f;
#pragma unroll
        for (int j = 0; j < 8; j++) {
            sf[j][0] = __expf(sf[j][0] - mn_lo);
            sf[j][1] = __expf(sf[j][1] - mn_lo);
            sf[j][2] = __expf(sf[j][2] - mn_hi);
            sf[j][3] = __expf(sf[j][3] - mn_hi);
            ps_lo += sf[j][0] + sf[j][1];
            ps_hi += sf[j][2] + sf[j][3];
        }
        ps_lo += __shfl_xor_sync(0xffffffffu, ps_lo, 1);
        ps_lo += __shfl_xor_sync(0xffffffffu, ps_lo, 2);
        ps_hi += __shfl_xor_sync(0xffffffffu, ps_hi, 1);
        ps_hi += __shfl_xor_sync(0xffffffffu, ps_hi, 2);
        l_lo = l_lo * alpha_lo + ps_lo;
        l_hi = l_hi * alpha_hi + ps_hi;
        m_lo = mn_lo; m_hi = mn_hi;

        // ---- P store: [q][tok] stride 272B, warp-local rows (q0..q0+15) ----
#pragma unroll
        for (int j = 0; j < 8; j++) {
            uint32_t base = QPO + (uint32_t)(q0 + g)*272 + 16*j + 4*c;
            *(uint32_t*)(sma + base)       = pkh2(sf[j][0], sf[j][1]);
            *(uint32_t*)(sma + base + 8*272) = pkh2(sf[j][2], sf[j][3]);
        }
        __syncwarp();

        // ---- O = O*alpha + P @ V  (A=P via ldsm, B=V via ldsm.trans) ----
#pragma unroll
        for (int j = 0; j < 8; j++) {
            of[j][0] *= alpha_lo; of[j][1] *= alpha_lo;
            of[j][2] *= alpha_hi; of[j][3] *= alpha_hi;
        }
#pragma unroll
        for (int kk = 0; kk < 4; kk++) {   // tok-chunks of 16
            uint32_t pa[4];
            ldsm4(pa, sbase + QPO + (uint32_t)(q0 + (lane & 15))*272 + (lane >> 4)*16 + kk*32);
#pragma unroll
            for (int dd = 0; dd < 4; dd++) {
                uint32_t r[4];
                ldsm4t(r, sbase + Vo + (uint32_t)(kk*16 + v_row)*144 + dd*32 + v_half);
                uint32_t b0[2] = { r[0], r[1] };
                uint32_t b1[2] = { r[2], r[3] };
                mma_f16(of[2*dd],   pa, b0);
                mma_f16(of[2*dd+1], pa, b1);
            }
        }

        __syncthreads();
        if (kt + 2 < SEQ/64) kvissue(kt + 2);
        CP_COMMIT();
    }

    // ---- epilogue: fp16 out (consumed by o-proj GEMM) ----
    float il_lo = 1.f / l_lo, il_hi = 1.f / l_hi;
#pragma unroll
    for (int dj = 0; dj < 8; dj++) {
        int col = col0 + 8*dj + 2*c;
        Og[((size_t)(base_q + q0 + g)*EMBED + col) >> 1]     = pkh2(of[dj][0]*il_lo, of[dj][1]*il_lo);
        Og[((size_t)(base_q + q0 + g + 8)*EMBED + col) >> 1] = pkh2(of[dj][2]*il_hi, of[dj][3]*il_hi);
    }
}

// ---------------- launch ----------------
extern "C" void kernel_launch(void* const* d_in, const int* in_sizes, int n_in,
                              void* d_out, int out_size) {
    const float* x  = (const float*)d_in[0];
    const float* Wq = (const float*)d_in[1];
    const float* bq = (const float*)d_in[2];
    const float* Aq = (const float*)d_in[3];
    const float* Bq = (const float*)d_in[4];
    const float* Wk = (const float*)d_in[5];
    const float* bk = (const float*)d_in[6];
    const float* Ak = (const float*)d_in[7];
    const float* Bk = (const float*)d_in[8];
    const float* Wv = (const float*)d_in[9];
    const float* bv = (const float*)d_in[10];
    const float* Av = (const float*)d_in[11];
    const float* Bv = (const float*)d_in[12];
    const float* Wo = (const float*)d_in[13];
    const float* bo = (const float*)d_in[14];
    const float* Ao = (const float*)d_in[15];
    const float* Bo = (const float*)d_in[16];
    float* out = (float*)d_out;

    uint32_t *Weff, *xt, *Q, *K, *V, *attn;
    cudaGetSymbolAddress((void**)&Weff, g_Weff);
    cudaGetSymbolAddress((void**)&xt, g_xt);
    cudaGetSymbolAddress((void**)&Q, g_Q);
    cudaGetSymbolAddress((void**)&K, g_K);
    cudaGetSymbolAddress((void**)&V, g_V);
    cudaGetSymbolAddress((void**)&attn, g_attn);

    // 0) x -> fp16
    xconv<<<TOKENS*EMBED/4/256, 256>>>((const float4*)x, (uint2*)xt);

    // 1) fold LoRA into effective fp16 weights (Q weights pre-scaled by 0.125)
    dim3 fgrid(EMBED*EMBED/2/256, 4);
    fold4_kernel<<<fgrid, 256>>>(Wq, Aq, Bq, Wk, Ak, Bk, Wv, Av, Bv, Wo, Ao, Bo);

    // 2) fused Q/K/V projections
    cudaFuncSetAttribute(gemm_tc<0>, cudaFuncAttributeMaxDynamicSharedMemorySize, GEMM_SMEM);
    cudaFuncSetAttribute(gemm_tc<1>, cudaFuncAttributeMaxDynamicSharedMemorySize, GEMM_SMEM);
    dim3 qkv_grid(EMBED/128, TOKENS/128, 3);
    gemm_tc<0><<<qkv_grid, 128, GEMM_SMEM>>>((const __half*)xt, (const __half*)Weff,
                                             bq, bk, bv, Q, K, V, nullptr);

    // 3) attention
    cudaFuncSetAttribute(attn_tc, cudaFuncAttributeMaxDynamicSharedMemorySize, ATTN_SMEM);
    dim3 agrid(SEQ/128, HEADS, NBATCH);
    attn_tc<<<agrid, 256, ATTN_SMEM>>>((const __half*)Q, (const __half*)K, (const __half*)V, attn);

    // 4) output projection (fp32 out + bias)
    dim3 ogrid(EMBED/128, TOKENS/128, 1);
    gemm_tc<1><<<ogrid, 128, GEMM_SMEM>>>((const __half*)attn,
                                          (const __half*)(Weff + 3*(size_t)(EMBED*EMBED/2)),
                                          bo, bo, bo, nullptr, nullptr, nullptr, out);
}

// round 7
// speedup vs baseline: 16.6924x; 1.2826x over previous
#include <cuda_runtime.h>
#include <cuda_fp16.h>
#include <math.h>
#include <stdint.h>

#define EMBED   1024
#define RANK    8
#define HEADS   16
#define HDIM    64
#define NBATCH  2
#define SEQ     2048
#define TOKENS  (NBATCH*SEQ)
#define LORA_SCALE 2.0f
#define LOG2E   1.44269504088896f

// ---------------- scratch (fp16 pairs stored as uint32) ----------------
__device__ uint32_t g_Weff[4][EMBED*EMBED/2];
__device__ uint32_t g_xt[TOKENS*EMBED/2];
__device__ uint32_t g_Q[TOKENS*EMBED/2];
__device__ uint32_t g_K[TOKENS*EMBED/2];
__device__ uint32_t g_V[TOKENS*EMBED/2];
__device__ uint32_t g_attn[TOKENS*EMBED/2];

// ---------------- helpers ----------------
__device__ __forceinline__ uint32_t pkh2(float a, float b) {
    __half2 h = __floats2half2_rn(a, b);
    return *(uint32_t*)&h;
}
__device__ __forceinline__ void mma_f16(float c[4], const uint32_t a[4], const uint32_t b[2]) {
    asm volatile("mma.sync.aligned.m16n8k16.row.col.f32.f16.f16.f32 "
        "{%0,%1,%2,%3}, {%4,%5,%6,%7}, {%8,%9}, {%0,%1,%2,%3};"
        : "+f"(c[0]), "+f"(c[1]), "+f"(c[2]), "+f"(c[3])
        : "r"(a[0]), "r"(a[1]), "r"(a[2]), "r"(a[3]), "r"(b[0]), "r"(b[1]));
}
__device__ __forceinline__ void ldsm4(uint32_t r[4], uint32_t addr) {
    asm volatile("ldmatrix.sync.aligned.m8n8.x4.shared.b16 {%0,%1,%2,%3}, [%4];"
        : "=r"(r[0]), "=r"(r[1]), "=r"(r[2]), "=r"(r[3]) : "r"(addr));
}
__device__ __forceinline__ void ldsm4t(uint32_t r[4], uint32_t addr) {
    asm volatile("ldmatrix.sync.aligned.m8n8.x4.trans.shared.b16 {%0,%1,%2,%3}, [%4];"
        : "=r"(r[0]), "=r"(r[1]), "=r"(r[2]), "=r"(r[3]) : "r"(addr));
}
__device__ __forceinline__ void cp16(uint32_t saddr, const void* gaddr) {
    asm volatile("cp.async.cg.shared.global [%0], [%1], 16;" :: "r"(saddr), "l"(gaddr));
}
#define CP_COMMIT() asm volatile("cp.async.commit_group;")
template<int N> __device__ __forceinline__ void cp_wait() {
    asm volatile("cp.async.wait_group %0;" :: "n"(N));
}

// ---------------- xconv: fp32 -> fp16 ----------------
__global__ void xconv(const float4* __restrict__ in, uint2* __restrict__ out) {
    int i = blockIdx.x * blockDim.x + threadIdx.x;
    float4 v = in[i];
    out[i] = make_uint2(pkh2(v.x, v.y), pkh2(v.z, v.w));
}

// ---------------- fold: Weff[z] = h(wscale * (W + 2 * B @ A)) ----------------
// z==0 (Q) folds 1/sqrt(64) * log2(e) so softmax can use exp2.
__global__ void fold4_kernel(const float* __restrict__ W0, const float* __restrict__ A0, const float* __restrict__ B0,
                             const float* __restrict__ W1, const float* __restrict__ A1, const float* __restrict__ B1,
                             const float* __restrict__ W2, const float* __restrict__ A2, const float* __restrict__ B2,
                             const float* __restrict__ W3, const float* __restrict__ A3, const float* __restrict__ B3) {
    int z = blockIdx.y;
    const float *W, *A, *B;
    if (z == 0) { W = W0; A = A0; B = B0; }
    else if (z == 1) { W = W1; A = A1; B = B1; }
    else if (z == 2) { W = W2; A = A2; B = B2; }
    else { W = W3; A = A3; B = B3; }
    float wscale = (z == 0) ? 0.125f * LOG2E : 1.0f;
    uint32_t* out = g_Weff[z];
    int idx = blockIdx.x * blockDim.x + threadIdx.x;   // pair index
    int o = idx >> 9;
    int i = (idx & 511) * 2;
    float s0 = 0.f, s1 = 0.f;
#pragma unroll
    for (int r = 0; r < RANK; r++) {
        float br = B[o*RANK + r];
        s0 = fmaf(br, A[r*EMBED + i],   s0);
        s1 = fmaf(br, A[r*EMBED + i+1], s1);
    }
    out[idx] = pkh2(wscale * (W[o*EMBED + i]   + LORA_SCALE * s0),
                    wscale * (W[o*EMBED + i+1] + LORA_SCALE * s1));
}

// ---------------- fp16 GEMM: C[M,N] = A[M,K] @ Bw[N,K]^T + bias ----------------
// CTA 128x128, 256 threads (8 warps, warp tile 32x64), 3-stage cp.async k32/stage.
// smem row stride 80B -> ldmatrix conflict-free.
#define GSTAGE 20480
#define GEMM_SMEM (3*GSTAGE)
template<int MODE>
__global__ __launch_bounds__(256)
void gemm_tc(const __half* __restrict__ A, const __half* __restrict__ Wbase,
             const float* __restrict__ bz0, const float* __restrict__ bz1, const float* __restrict__ bz2,
             uint32_t* __restrict__ o0, uint32_t* __restrict__ o1, uint32_t* __restrict__ o2,
             float* __restrict__ ofp) {
    extern __shared__ char smg[];
    const int z = (MODE == 0) ? blockIdx.z : 0;
    const __half* Bw = Wbase + (size_t)z * (EMBED*EMBED);
    const float* bias = (z == 0) ? bz0 : (z == 1) ? bz1 : bz2;
    const float bscale = (MODE == 0 && z == 0) ? 0.125f * LOG2E : 1.0f;
    uint32_t* Ch = (z == 0) ? o0 : (z == 1) ? o1 : o2;

    const int tid = threadIdx.x, warp = tid >> 5, lane = tid & 31;
    const int g = lane >> 2, c = lane & 3;
    const int wm = (warp & 3) * 32, wn = (warp >> 2) * 64;
    const int m0 = blockIdx.y * 128, n0 = blockIdx.x * 128;

    const uint32_t sbase = (uint32_t)__cvta_generic_to_shared(smg);

    auto issue = [&](int s) {
        uint32_t off = sbase + (uint32_t)(s % 3) * GSTAGE;
#pragma unroll
        for (int p = 0; p < 2; p++) {
            int idx = tid + 256*p;             // 0..511
            int row = idx >> 2, part = idx & 3;
            cp16(off + row*80 + part*16,
                 A  + (size_t)(m0 + row)*EMBED + s*32 + part*8);
            cp16(off + 10240 + row*80 + part*16,
                 Bw + (size_t)(n0 + row)*EMBED + s*32 + part*8);
        }
    };

    float acc[2][8][4];
#pragma unroll
    for (int t = 0; t < 2; t++)
#pragma unroll
        for (int j = 0; j < 8; j++)
#pragma unroll
            for (int r = 0; r < 4; r++) acc[t][j][r] = 0.f;

    const int a_row  = lane & 15;
    const int a_half = (lane >> 4) * 16;
    const int b_row  = (lane & 7) + ((lane >> 4) << 3);
    const int b_half = ((lane >> 3) & 1) * 16;

    issue(0); CP_COMMIT();
    issue(1); CP_COMMIT();

    for (int s = 0; s < EMBED/32; s++) {
        cp_wait<1>(); __syncthreads();
        if (s + 2 < EMBED/32) issue(s + 2);
        CP_COMMIT();

        uint32_t offA = sbase + (uint32_t)(s % 3) * GSTAGE;
        uint32_t offB = offA + 10240;

#pragma unroll
        for (int kk = 0; kk < 2; kk++) {
            uint32_t af[2][4], bf[8][2];
#pragma unroll
            for (int t = 0; t < 2; t++)
                ldsm4(af[t], offA + (uint32_t)(wm + 16*t + a_row)*80 + a_half + kk*32);
#pragma unroll
            for (int jj = 0; jj < 4; jj++) {
                uint32_t r[4];
                ldsm4(r, offB + (uint32_t)(wn + 16*jj + b_row)*80 + b_half + kk*32);
                bf[2*jj][0] = r[0]; bf[2*jj][1] = r[1];
                bf[2*jj+1][0] = r[2]; bf[2*jj+1][1] = r[3];
            }
#pragma unroll
            for (int t = 0; t < 2; t++)
#pragma unroll
                for (int j = 0; j < 8; j++)
                    mma_f16(acc[t][j], af[t], bf[j]);
        }
    }

    // epilogue
#pragma unroll
    for (int j = 0; j < 8; j++) {
        int col = n0 + wn + 8*j + 2*c;
        float bv0 = bias[col] * bscale, bv1 = bias[col + 1] * bscale;
#pragma unroll
        for (int t = 0; t < 2; t++) {
            int row0 = m0 + wm + 16*t + g;
            float v00 = acc[t][j][0] + bv0, v01 = acc[t][j][1] + bv1;
            float v10 = acc[t][j][2] + bv0, v11 = acc[t][j][3] + bv1;
            if (MODE == 1) {
                *(float2*)(ofp + (size_t)row0*EMBED + col)     = make_float2(v00, v01);
                *(float2*)(ofp + (size_t)(row0+8)*EMBED + col) = make_float2(v10, v11);
            } else {
                Ch[((size_t)row0*EMBED + col) >> 1]     = pkh2(v00, v01);
                Ch[((size_t)(row0+8)*EMBED + col) >> 1] = pkh2(v10, v11);
            }
        }
    }
}

// ---------------- flash attention, fp16 mma, register-resident P ----------------
// 128 q/CTA, 8 warps (16 q each), key tiles of 64, 3-stage K/V, ONE barrier/tile.
// smem: K 3x[64][144B], V 3x[64][144B], Q [128][144B]  = 73728 B
#define KOB(s)  ((uint32_t)(s)*9216u)
#define VOB(s)  (27648u + (uint32_t)(s)*9216u)
#define QO      55296u
#define ATTN_SMEM (55296 + 18432)   // 73728 B

__global__ __launch_bounds__(256, 2)
void attn_tc(const __half* __restrict__ Qg, const __half* __restrict__ Kg,
             const __half* __restrict__ Vg, uint32_t* __restrict__ Og) {
    extern __shared__ char sma[];
    const uint32_t sbase = (uint32_t)__cvta_generic_to_shared(sma);

    const int qt = blockIdx.x, h = blockIdx.y, nb = blockIdx.z;
    const int tid = threadIdx.x, warp = tid >> 5, lane = tid & 31;
    const int g = lane >> 2, c = lane & 3;
    const int q0 = warp * 16;
    const int base_q = nb*SEQ + qt*128;
    const int col0 = h * HDIM;

    auto kvissue = [&](int kt) {
        int s = kt % 3;
        int base_k = nb*SEQ + kt*64;
#pragma unroll
        for (int p = 0; p < 2; p++) {
            int idx = tid + 256*p;            // 0..511
            int row = idx >> 3, q = idx & 7;
            cp16(sbase + KOB(s) + row*144 + q*16,
                 Kg + (size_t)(base_k + row)*EMBED + col0 + 8*q);
        }
#pragma unroll
        for (int p = 0; p < 2; p++) {
            int idx = tid + 256*p;
            int row = idx >> 3, q = idx & 7;
            cp16(sbase + VOB(s) + row*144 + q*16,
                 Vg + (size_t)(base_k + row)*EMBED + col0 + 8*q);
        }
    };

    // Q tile (128 rows x 64 halves), stride 144B
#pragma unroll
    for (int p = 0; p < 4; p++) {
        int idx = tid + 256*p;                // 0..1023
        int row = idx >> 3, q = idx & 7;
        cp16(sbase + QO + row*144 + q*16,
             Qg + (size_t)(base_q + row)*EMBED + col0 + 8*q);
    }
    CP_COMMIT();
    kvissue(0); CP_COMMIT();
    kvissue(1); CP_COMMIT();

    cp_wait<2>(); __syncthreads();   // Q ready (all threads' Q groups drained)

    const int b_row  = (lane & 7) + ((lane >> 4) << 3);       // non-trans B rows
    const int b_half = ((lane >> 3) & 1) * 16;
    const int v_row  = (lane & 7) + (((lane >> 3) & 1) << 3); // trans V rows
    const int v_half = (lane >> 4) * 16;

    uint32_t qf[4][4];
#pragma unroll
    for (int kk = 0; kk < 4; kk++)
        ldsm4(qf[kk], sbase + QO + (uint32_t)(q0 + (lane & 15))*144 + (lane >> 4)*16 + kk*32);

    float of[8][4];
#pragma unroll
    for (int j = 0; j < 8; j++)
#pragma unroll
        for (int r = 0; r < 4; r++) of[j][r] = 0.f;
    float m_lo = -1e30f, m_hi = -1e30f, l_lo = 0.f, l_hi = 0.f;

    for (int kt = 0; kt < SEQ/64; kt++) {
        cp_wait<1>(); __syncthreads();    // tile kt ready; all warps finished kt-1
        if (kt + 2 < SEQ/64) kvissue(kt + 2);
        CP_COMMIT();
        const uint32_t Ko = KOB(kt % 3);
        const uint32_t Vo = VOB(kt % 3);

        // ---- S = Q @ K^T (already in log2-e domain via folded Q scale) ----
        float sf[8][4];
#pragma unroll
        for (int j = 0; j < 8; j++)
#pragma unroll
            for (int r = 0; r < 4; r++) sf[j][r] = 0.f;
#pragma unroll
        for (int kk = 0; kk < 4; kk++) {
            uint32_t bf[8][2];
#pragma unroll
            for (int jj = 0; jj < 4; jj++) {
                uint32_t r[4];
                ldsm4(r, sbase + Ko + (uint32_t)(16*jj + b_row)*144 + b_half + kk*32);
                bf[2*jj][0] = r[0]; bf[2*jj][1] = r[1];
                bf[2*jj+1][0] = r[2]; bf[2*jj+1][1] = r[3];
            }
#pragma unroll
            for (int j = 0; j < 8; j++)
                mma_f16(sf[j], qf[kk], bf[j]);
        }

        // ---- online softmax (base-2) ----
        float mx_lo = -1e30f, mx_hi = -1e30f;
#pragma unroll
        for (int j = 0; j < 8; j++) {
            mx_lo = fmaxf(mx_lo, fmaxf(sf[j][0], sf[j][1]));
            mx_hi = fmaxf(mx_hi, fmaxf(sf[j][2], sf[j][3]));
        }
        mx_lo = fmaxf(mx_lo, __shfl_xor_sync(0xffffffffu, mx_lo, 1));
        mx_lo = fmaxf(mx_lo, __shfl_xor_sync(0xffffffffu, mx_lo, 2));
        mx_hi = fmaxf(mx_hi, __shfl_xor_sync(0xffffffffu, mx_hi, 1));
        mx_hi = fmaxf(mx_hi, __shfl_xor_sync(0xffffffffu, mx_hi, 2));

        float mn_lo = fmaxf(m_lo, mx_lo);
        float mn_hi = fmaxf(m_hi, mx_hi);
        float alpha_lo = exp2f(m_lo - mn_lo);
        float alpha_hi = exp2f(m_hi - mn_hi);

        float ps_lo = 0.f, ps_hi = 0.f;
#pragma unroll
        for (int j = 0; j < 8; j++) {
            sf[j][0] = exp2f(sf[j][0] - mn_lo);
            sf[j][1] = exp2f(sf[j][1] - mn_lo);
            sf[j][2] = exp2f(sf[j][2] - mn_hi);
            sf[j][3] = exp2f(sf[j][3] - mn_hi);
            ps_lo += sf[j][0] + sf[j][1];
            ps_hi += sf[j][2] + sf[j][3];
        }
        ps_lo += __shfl_xor_sync(0xffffffffu, ps_lo, 1);
        ps_lo += __shfl_xor_sync(0xffffffffu, ps_lo, 2);
        ps_hi += __shfl_xor_sync(0xffffffffu, ps_hi, 1);
        ps_hi += __shfl_xor_sync(0xffffffffu, ps_hi, 2);
        l_lo = l_lo * alpha_lo + ps_lo;
        l_hi = l_hi * alpha_hi + ps_hi;
        m_lo = mn_lo; m_hi = mn_hi;

        // ---- P: repack S C-frags directly into PV A-frags (NO smem) ----
        uint32_t pa[4][4];
#pragma unroll
        for (int kk = 0; kk < 4; kk++) {
            pa[kk][0] = pkh2(sf[2*kk][0],   sf[2*kk][1]);
            pa[kk][1] = pkh2(sf[2*kk][2],   sf[2*kk][3]);
            pa[kk][2] = pkh2(sf[2*kk+1][0], sf[2*kk+1][1]);
            pa[kk][3] = pkh2(sf[2*kk+1][2], sf[2*kk+1][3]);
        }

        // ---- O = O*alpha + P @ V  (B=V via ldsm.trans) ----
#pragma unroll
        for (int j = 0; j < 8; j++) {
            of[j][0] *= alpha_lo; of[j][1] *= alpha_lo;
            of[j][2] *= alpha_hi; of[j][3] *= alpha_hi;
        }
#pragma unroll
        for (int kk = 0; kk < 4; kk++) {   // tok-chunks of 16
#pragma unroll
            for (int dd = 0; dd < 4; dd++) {
                uint32_t r[4];
                ldsm4t(r, sbase + Vo + (uint32_t)(kk*16 + v_row)*144 + dd*32 + v_half);
                uint32_t b0[2] = { r[0], r[1] };
                uint32_t b1[2] = { r[2], r[3] };
                mma_f16(of[2*dd],   pa[kk], b0);
                mma_f16(of[2*dd+1], pa[kk], b1);
            }
        }
    }

    // ---- epilogue: fp16 out (consumed by o-proj GEMM) ----
    float il_lo = 1.f / l_lo, il_hi = 1.f / l_hi;
#pragma unroll
    for (int dj = 0; dj < 8; dj++) {
        int col = col0 + 8*dj + 2*c;
        Og[((size_t)(base_q + q0 + g)*EMBED + col) >> 1]     = pkh2(of[dj][0]*il_lo, of[dj][1]*il_lo);
        Og[((size_t)(base_q + q0 + g + 8)*EMBED + col) >> 1] = pkh2(of[dj][2]*il_hi, of[dj][3]*il_hi);
    }
}

// ---------------- launch ----------------
extern "C" void kernel_launch(void* const* d_in, const int* in_sizes, int n_in,
                              void* d_out, int out_size) {
    const float* x  = (const float*)d_in[0];
    const float* Wq = (const float*)d_in[1];
    const float* bq = (const float*)d_in[2];
    const float* Aq = (const float*)d_in[3];
    const float* Bq = (const float*)d_in[4];
    const float* Wk = (const float*)d_in[5];
    const float* bk = (const float*)d_in[6];
    const float* Ak = (const float*)d_in[7];
    const float* Bk = (const float*)d_in[8];
    const float* Wv = (const float*)d_in[9];
    const float* bv = (const float*)d_in[10];
    const float* Av = (const float*)d_in[11];
    const float* Bv = (const float*)d_in[12];
    const float* Wo = (const float*)d_in[13];
    const float* bo = (const float*)d_in[14];
    const float* Ao = (const float*)d_in[15];
    const float* Bo = (const float*)d_in[16];
    float* out = (float*)d_out;

    uint32_t *Weff, *xt, *Q, *K, *V, *attn;
    cudaGetSymbolAddress((void**)&Weff, g_Weff);
    cudaGetSymbolAddress((void**)&xt, g_xt);
    cudaGetSymbolAddress((void**)&Q, g_Q);
    cudaGetSymbolAddress((void**)&K, g_K);
    cudaGetSymbolAddress((void**)&V, g_V);
    cudaGetSymbolAddress((void**)&attn, g_attn);

    // 0) x -> fp16
    xconv<<<TOKENS*EMBED/4/256, 256>>>((const float4*)x, (uint2*)xt);

    // 1) fold LoRA into effective fp16 weights (Q pre-scaled by 0.125*log2e)
    dim3 fgrid(EMBED*EMBED/2/256, 4);
    fold4_kernel<<<fgrid, 256>>>(Wq, Aq, Bq, Wk, Ak, Bk, Wv, Av, Bv, Wo, Ao, Bo);

    // 2) fused Q/K/V projections
    cudaFuncSetAttribute(gemm_tc<0>, cudaFuncAttributeMaxDynamicSharedMemorySize, GEMM_SMEM);
    cudaFuncSetAttribute(gemm_tc<1>, cudaFuncAttributeMaxDynamicSharedMemorySize, GEMM_SMEM);
    dim3 qkv_grid(EMBED/128, TOKENS/128, 3);
    gemm_tc<0><<<qkv_grid, 256, GEMM_SMEM>>>((const __half*)xt, (const __half*)Weff,
                                             bq, bk, bv, Q, K, V, nullptr);

    // 3) attention
    cudaFuncSetAttribute(attn_tc, cudaFuncAttributeMaxDynamicSharedMemorySize, ATTN_SMEM);
    dim3 agrid(SEQ/128, HEADS, NBATCH);
    attn_tc<<<agrid, 256, ATTN_SMEM>>>((const __half*)Q, (const __half*)K, (const __half*)V, attn);

    // 4) output projection (fp32 out + bias)
    dim3 ogrid(EMBED/128, TOKENS/128, 1);
    gemm_tc<1><<<ogrid, 256, GEMM_SMEM>>>((const __half*)attn,
                                          (const __half*)(Weff + 3*(size_t)(EMBED*EMBED/2)),
                                          bo, bo, bo, nullptr, nullptr, nullptr, out);
}

// round 8
// speedup vs baseline: 16.6961x; 1.0002x over previous
#include <cuda_runtime.h>
#include <cuda_fp16.h>
#include <math.h>
#include <stdint.h>

#define EMBED   1024
#define RANK    8
#define HEADS   16
#define HDIM    64
#define NBATCH  2
#define SEQ     2048
#define TOKENS  (NBATCH*SEQ)
#define LORA_SCALE 2.0f
#define LOG2E   1.44269504088896f

// ---------------- scratch (fp16 pairs stored as uint32) ----------------
__device__ uint32_t g_Weff[4][EMBED*EMBED/2];
__device__ uint32_t g_xt[TOKENS*EMBED/2];
__device__ uint32_t g_Q[TOKENS*EMBED/2];
__device__ uint32_t g_K[TOKENS*EMBED/2];
__device__ uint32_t g_V[TOKENS*EMBED/2];
__device__ uint32_t g_attn[TOKENS*EMBED/2];

// ---------------- helpers ----------------
__device__ __forceinline__ uint32_t pkh2(float a, float b) {
    __half2 h = __floats2half2_rn(a, b);
    return *(uint32_t*)&h;
}
__device__ __forceinline__ void mma_f16(float c[4], const uint32_t a[4], const uint32_t b[2]) {
    asm volatile("mma.sync.aligned.m16n8k16.row.col.f32.f16.f16.f32 "
        "{%0,%1,%2,%3}, {%4,%5,%6,%7}, {%8,%9}, {%0,%1,%2,%3};"
        : "+f"(c[0]), "+f"(c[1]), "+f"(c[2]), "+f"(c[3])
        : "r"(a[0]), "r"(a[1]), "r"(a[2]), "r"(a[3]), "r"(b[0]), "r"(b[1]));
}
__device__ __forceinline__ void ldsm4(uint32_t r[4], uint32_t addr) {
    asm volatile("ldmatrix.sync.aligned.m8n8.x4.shared.b16 {%0,%1,%2,%3}, [%4];"
        : "=r"(r[0]), "=r"(r[1]), "=r"(r[2]), "=r"(r[3]) : "r"(addr));
}
__device__ __forceinline__ void ldsm4t(uint32_t r[4], uint32_t addr) {
    asm volatile("ldmatrix.sync.aligned.m8n8.x4.trans.shared.b16 {%0,%1,%2,%3}, [%4];"
        : "=r"(r[0]), "=r"(r[1]), "=r"(r[2]), "=r"(r[3]) : "r"(addr));
}
__device__ __forceinline__ void cp16(uint32_t saddr, const void* gaddr) {
    asm volatile("cp.async.cg.shared.global [%0], [%1], 16;" :: "r"(saddr), "l"(gaddr));
}
#define CP_COMMIT() asm volatile("cp.async.commit_group;")
template<int N> __device__ __forceinline__ void cp_wait() {
    asm volatile("cp.async.wait_group %0;" :: "n"(N));
}

// ---------------- xconv: fp32 -> fp16 ----------------
__global__ void xconv(const float4* __restrict__ in, uint2* __restrict__ out) {
    int i = blockIdx.x * blockDim.x + threadIdx.x;
    float4 v = in[i];
    out[i] = make_uint2(pkh2(v.x, v.y), pkh2(v.z, v.w));
}

// ---------------- fold: Weff[z] = h(wscale * (W + 2 * B @ A)) ----------------
__global__ void fold4_kernel(const float* __restrict__ W0, const float* __restrict__ A0, const float* __restrict__ B0,
                             const float* __restrict__ W1, const float* __restrict__ A1, const float* __restrict__ B1,
                             const float* __restrict__ W2, const float* __restrict__ A2, const float* __restrict__ B2,
                             const float* __restrict__ W3, const float* __restrict__ A3, const float* __restrict__ B3) {
    int z = blockIdx.y;
    const float *W, *A, *B;
    if (z == 0) { W = W0; A = A0; B = B0; }
    else if (z == 1) { W = W1; A = A1; B = B1; }
    else if (z == 2) { W = W2; A = A2; B = B2; }
    else { W = W3; A = A3; B = B3; }
    float wscale = (z == 0) ? 0.125f * LOG2E : 1.0f;
    uint32_t* out = g_Weff[z];
    int idx = blockIdx.x * blockDim.x + threadIdx.x;
    int o = idx >> 9;
    int i = (idx & 511) * 2;
    float s0 = 0.f, s1 = 0.f;
#pragma unroll
    for (int r = 0; r < RANK; r++) {
        float br = B[o*RANK + r];
        s0 = fmaf(br, A[r*EMBED + i],   s0);
        s1 = fmaf(br, A[r*EMBED + i+1], s1);
    }
    out[idx] = pkh2(wscale * (W[o*EMBED + i]   + LORA_SCALE * s0),
                    wscale * (W[o*EMBED + i+1] + LORA_SCALE * s1));
}

// ---------------- fp16 GEMM: C[M,N] = A[M,K] @ Bw[N,K]^T + bias ----------------
// CTA 128x128, 256 threads (8 warps, warp tile 32x64), 4-stage cp.async k32/stage.
#define GSTAGE 20480
#define GEMM_SMEM (4*GSTAGE)   // 81920
template<int MODE>
__global__ __launch_bounds__(256)
void gemm_tc(const __half* __restrict__ A, const __half* __restrict__ Wbase,
             const float* __restrict__ bz0, const float* __restrict__ bz1, const float* __restrict__ bz2,
             uint32_t* __restrict__ o0, uint32_t* __restrict__ o1, uint32_t* __restrict__ o2,
             float* __restrict__ ofp) {
    extern __shared__ char smg[];
    const int z = (MODE == 0) ? blockIdx.z : 0;
    const __half* Bw = Wbase + (size_t)z * (EMBED*EMBED);
    const float* bias = (z == 0) ? bz0 : (z == 1) ? bz1 : bz2;
    const float bscale = (MODE == 0 && z == 0) ? 0.125f * LOG2E : 1.0f;
    uint32_t* Ch = (z == 0) ? o0 : (z == 1) ? o1 : o2;

    const int tid = threadIdx.x, warp = tid >> 5, lane = tid & 31;
    const int g = lane >> 2, c = lane & 3;
    const int wm = (warp & 3) * 32, wn = (warp >> 2) * 64;
    const int m0 = blockIdx.y * 128, n0 = blockIdx.x * 128;

    const uint32_t sbase = (uint32_t)__cvta_generic_to_shared(smg);

    auto issue = [&](int s) {
        uint32_t off = sbase + (uint32_t)(s & 3) * GSTAGE;
#pragma unroll
        for (int p = 0; p < 2; p++) {
            int idx = tid + 256*p;
            int row = idx >> 2, part = idx & 3;
            cp16(off + row*80 + part*16,
                 A  + (size_t)(m0 + row)*EMBED + s*32 + part*8);
            cp16(off + 10240 + row*80 + part*16,
                 Bw + (size_t)(n0 + row)*EMBED + s*32 + part*8);
        }
    };

    float acc[2][8][4];
#pragma unroll
    for (int t = 0; t < 2; t++)
#pragma unroll
        for (int j = 0; j < 8; j++)
#pragma unroll
            for (int r = 0; r < 4; r++) acc[t][j][r] = 0.f;

    const int a_row  = lane & 15;
    const int a_half = (lane >> 4) * 16;
    const int b_row  = (lane & 7) + ((lane >> 4) << 3);
    const int b_half = ((lane >> 3) & 1) * 16;

    issue(0); CP_COMMIT();
    issue(1); CP_COMMIT();
    issue(2); CP_COMMIT();

    for (int s = 0; s < EMBED/32; s++) {
        cp_wait<2>(); __syncthreads();
        if (s + 3 < EMBED/32) issue(s + 3);
        CP_COMMIT();

        uint32_t offA = sbase + (uint32_t)(s & 3) * GSTAGE;
        uint32_t offB = offA + 10240;

#pragma unroll
        for (int kk = 0; kk < 2; kk++) {
            uint32_t af[2][4], bf[8][2];
#pragma unroll
            for (int t = 0; t < 2; t++)
                ldsm4(af[t], offA + (uint32_t)(wm + 16*t + a_row)*80 + a_half + kk*32);
#pragma unroll
            for (int jj = 0; jj < 4; jj++) {
                uint32_t r[4];
                ldsm4(r, offB + (uint32_t)(wn + 16*jj + b_row)*80 + b_half + kk*32);
                bf[2*jj][0] = r[0]; bf[2*jj][1] = r[1];
                bf[2*jj+1][0] = r[2]; bf[2*jj+1][1] = r[3];
            }
#pragma unroll
            for (int t = 0; t < 2; t++)
#pragma unroll
                for (int j = 0; j < 8; j++)
                    mma_f16(acc[t][j], af[t], bf[j]);
        }
    }

    // epilogue
#pragma unroll
    for (int j = 0; j < 8; j++) {
        int col = n0 + wn + 8*j + 2*c;
        float bv0 = bias[col] * bscale, bv1 = bias[col + 1] * bscale;
#pragma unroll
        for (int t = 0; t < 2; t++) {
            int row0 = m0 + wm + 16*t + g;
            float v00 = acc[t][j][0] + bv0, v01 = acc[t][j][1] + bv1;
            float v10 = acc[t][j][2] + bv0, v11 = acc[t][j][3] + bv1;
            if (MODE == 1) {
                *(float2*)(ofp + (size_t)row0*EMBED + col)     = make_float2(v00, v01);
                *(float2*)(ofp + (size_t)(row0+8)*EMBED + col) = make_float2(v10, v11);
            } else {
                Ch[((size_t)row0*EMBED + col) >> 1]     = pkh2(v00, v01);
                Ch[((size_t)(row0+8)*EMBED + col) >> 1] = pkh2(v10, v11);
            }
        }
    }
}

// ---------------- flash attention, fp16 mma, pipelined S, ones-mma l ----------------
// 128 q/CTA, 8 warps (16 q each), key tiles of 64, 4-slot K/V ring.
// smem: K 4x[64][144B], V 4x[64][144B], Q [128][144B] = 92160 B
#define KOB(s)  ((uint32_t)(s)*9216u)
#define VOB(s)  (36864u + (uint32_t)(s)*9216u)
#define QO      73728u
#define ATTN_SMEM (73728 + 18432)   // 92160
#define NT (SEQ/64)

__global__ __launch_bounds__(256, 2)
void attn_tc(const __half* __restrict__ Qg, const __half* __restrict__ Kg,
             const __half* __restrict__ Vg, uint32_t* __restrict__ Og) {
    extern __shared__ char sma[];
    const uint32_t sbase = (uint32_t)__cvta_generic_to_shared(sma);

    const int qt = blockIdx.x, h = blockIdx.y, nb = blockIdx.z;
    const int tid = threadIdx.x, warp = tid >> 5, lane = tid & 31;
    const int g = lane >> 2, c = lane & 3;
    const int q0 = warp * 16;
    const int base_q = nb*SEQ + qt*128;
    const int col0 = h * HDIM;

    auto kvissue = [&](int kt) {
        int s = kt & 3;
        int base_k = nb*SEQ + kt*64;
#pragma unroll
        for (int p = 0; p < 2; p++) {
            int idx = tid + 256*p;
            int row = idx >> 3, q = idx & 7;
            cp16(sbase + KOB(s) + row*144 + q*16,
                 Kg + (size_t)(base_k + row)*EMBED + col0 + 8*q);
        }
#pragma unroll
        for (int p = 0; p < 2; p++) {
            int idx = tid + 256*p;
            int row = idx >> 3, q = idx & 7;
            cp16(sbase + VOB(s) + row*144 + q*16,
                 Vg + (size_t)(base_k + row)*EMBED + col0 + 8*q);
        }
    };

    // Q tile (128 rows x 64 halves), stride 144B
#pragma unroll
    for (int p = 0; p < 4; p++) {
        int idx = tid + 256*p;
        int row = idx >> 3, q = idx & 7;
        cp16(sbase + QO + row*144 + q*16,
             Qg + (size_t)(base_q + row)*EMBED + col0 + 8*q);
    }
    CP_COMMIT();
    kvissue(0); CP_COMMIT();
    kvissue(1); CP_COMMIT();
    kvissue(2); CP_COMMIT();

    const int b_row  = (lane & 7) + ((lane >> 4) << 3);
    const int b_half = ((lane >> 3) & 1) * 16;
    const int v_row  = (lane & 7) + (((lane >> 3) & 1) << 3);
    const int v_half = (lane >> 4) * 16;

    cp_wait<3>(); __syncthreads();   // Q done
    uint32_t qf[4][4];
#pragma unroll
    for (int kk = 0; kk < 4; kk++)
        ldsm4(qf[kk], sbase + QO + (uint32_t)(q0 + (lane & 15))*144 + (lane >> 4)*16 + kk*32);

    float sf[8][4];
    auto do_S = [&](uint32_t Ko) {
#pragma unroll
        for (int j = 0; j < 8; j++)
#pragma unroll
            for (int r = 0; r < 4; r++) sf[j][r] = 0.f;
#pragma unroll
        for (int kk = 0; kk < 4; kk++) {
            uint32_t bf[8][2];
#pragma unroll
            for (int jj = 0; jj < 4; jj++) {
                uint32_t r[4];
                ldsm4(r, sbase + Ko + (uint32_t)(16*jj + b_row)*144 + b_half + kk*32);
                bf[2*jj][0] = r[0]; bf[2*jj][1] = r[1];
                bf[2*jj+1][0] = r[2]; bf[2*jj+1][1] = r[3];
            }
#pragma unroll
            for (int j = 0; j < 8; j++)
                mma_f16(sf[j], qf[kk], bf[j]);
        }
    };

    cp_wait<2>(); __syncthreads();   // kv0 done
    do_S(KOB(0));                    // S(0)

    float of[8][4], of_l[4];
#pragma unroll
    for (int j = 0; j < 8; j++)
#pragma unroll
        for (int r = 0; r < 4; r++) of[j][r] = 0.f;
#pragma unroll
    for (int r = 0; r < 4; r++) of_l[r] = 0.f;
    float m_lo = -1e30f, m_hi = -1e30f;
    const uint32_t ones2 = 0x3C003C00u;

    for (int kt = 0; kt < NT; kt++) {
        // ---- softmax(kt) on sf (base-2 domain) ----
        float mx_lo = -1e30f, mx_hi = -1e30f;
#pragma unroll
        for (int j = 0; j < 8; j++) {
            mx_lo = fmaxf(mx_lo, fmaxf(sf[j][0], sf[j][1]));
            mx_hi = fmaxf(mx_hi, fmaxf(sf[j][2], sf[j][3]));
        }
        mx_lo = fmaxf(mx_lo, __shfl_xor_sync(0xffffffffu, mx_lo, 1));
        mx_lo = fmaxf(mx_lo, __shfl_xor_sync(0xffffffffu, mx_lo, 2));
        mx_hi = fmaxf(mx_hi, __shfl_xor_sync(0xffffffffu, mx_hi, 1));
        mx_hi = fmaxf(mx_hi, __shfl_xor_sync(0xffffffffu, mx_hi, 2));

        float mn_lo = fmaxf(m_lo, mx_lo);
        float mn_hi = fmaxf(m_hi, mx_hi);
        float alpha_lo = exp2f(m_lo - mn_lo);
        float alpha_hi = exp2f(m_hi - mn_hi);
        m_lo = mn_lo; m_hi = mn_hi;

        uint32_t pa[4][4];
#pragma unroll
        for (int kk = 0; kk < 4; kk++) {
            pa[kk][0] = pkh2(exp2f(sf[2*kk][0]   - mn_lo), exp2f(sf[2*kk][1]   - mn_lo));
            pa[kk][1] = pkh2(exp2f(sf[2*kk][2]   - mn_hi), exp2f(sf[2*kk][3]   - mn_hi));
            pa[kk][2] = pkh2(exp2f(sf[2*kk+1][0] - mn_lo), exp2f(sf[2*kk+1][1] - mn_lo));
            pa[kk][3] = pkh2(exp2f(sf[2*kk+1][2] - mn_hi), exp2f(sf[2*kk+1][3] - mn_hi));
        }

        // ---- advance pipeline: kv(kt+1) ready; refill slot; S(kt+1) ----
        cp_wait<1>(); __syncthreads();       // kv(kt+1) complete; all warps past PV(kt-1)
        if (kt + 3 < NT) kvissue(kt + 3);    // overwrites slot (kt-1)&3 (safe post-barrier)
        CP_COMMIT();
        if (kt + 1 < NT) do_S(KOB((kt + 1) & 3));   // sf <- S(kt+1), overlaps PV(kt) below

        // ---- O = O*alpha + P @ V ; l via ones-column mma ----
#pragma unroll
        for (int j = 0; j < 8; j++) {
            of[j][0] *= alpha_lo; of[j][1] *= alpha_lo;
            of[j][2] *= alpha_hi; of[j][3] *= alpha_hi;
        }
        of_l[0] *= alpha_lo; of_l[1] *= alpha_lo;
        of_l[2] *= alpha_hi; of_l[3] *= alpha_hi;

        const uint32_t Vo = VOB(kt & 3);
#pragma unroll
        for (int kk = 0; kk < 4; kk++) {
#pragma unroll
            for (int dd = 0; dd < 4; dd++) {
                uint32_t r[4];
                ldsm4t(r, sbase + Vo + (uint32_t)(kk*16 + v_row)*144 + dd*32 + v_half);
                uint32_t b0[2] = { r[0], r[1] };
                uint32_t b1[2] = { r[2], r[3] };
                mma_f16(of[2*dd],   pa[kk], b0);
                mma_f16(of[2*dd+1], pa[kk], b1);
            }
            uint32_t ob[2] = { ones2, ones2 };
            mma_f16(of_l, pa[kk], ob);
        }
    }

    // ---- epilogue: fp16 out (consumed by o-proj GEMM) ----
    float il_lo = 1.f / of_l[0], il_hi = 1.f / of_l[2];
#pragma unroll
    for (int dj = 0; dj < 8; dj++) {
        int col = col0 + 8*dj + 2*c;
        Og[((size_t)(base_q + q0 + g)*EMBED + col) >> 1]     = pkh2(of[dj][0]*il_lo, of[dj][1]*il_lo);
        Og[((size_t)(base_q + q0 + g + 8)*EMBED + col) >> 1] = pkh2(of[dj][2]*il_hi, of[dj][3]*il_hi);
    }
}

// ---------------- launch ----------------
extern "C" void kernel_launch(void* const* d_in, const int* in_sizes, int n_in,
                              void* d_out, int out_size) {
    const float* x  = (const float*)d_in[0];
    const float* Wq = (const float*)d_in[1];
    const float* bq = (const float*)d_in[2];
    const float* Aq = (const float*)d_in[3];
    const float* Bq = (const float*)d_in[4];
    const float* Wk = (const float*)d_in[5];
    const float* bk = (const float*)d_in[6];
    const float* Ak = (const float*)d_in[7];
    const float* Bk = (const float*)d_in[8];
    const float* Wv = (const float*)d_in[9];
    const float* bv = (const float*)d_in[10];
    const float* Av = (const float*)d_in[11];
    const float* Bv = (const float*)d_in[12];
    const float* Wo = (const float*)d_in[13];
    const float* bo = (const float*)d_in[14];
    const float* Ao = (const float*)d_in[15];
    const float* Bo = (const float*)d_in[16];
    float* out = (float*)d_out;

    uint32_t *Weff, *xt, *Q, *K, *V, *attn;
    cudaGetSymbolAddress((void**)&Weff, g_Weff);
    cudaGetSymbolAddress((void**)&xt, g_xt);
    cudaGetSymbolAddress((void**)&Q, g_Q);
    cudaGetSymbolAddress((void**)&K, g_K);
    cudaGetSymbolAddress((void**)&V, g_V);
    cudaGetSymbolAddress((void**)&attn, g_attn);

    // 0) x -> fp16
    xconv<<<TOKENS*EMBED/4/256, 256>>>((const float4*)x, (uint2*)xt);

    // 1) fold LoRA into effective fp16 weights (Q pre-scaled by 0.125*log2e)
    dim3 fgrid(EMBED*EMBED/2/256, 4);
    fold4_kernel<<<fgrid, 256>>>(Wq, Aq, Bq, Wk, Ak, Bk, Wv, Av, Bv, Wo, Ao, Bo);

    // 2) fused Q/K/V projections
    cudaFuncSetAttribute(gemm_tc<0>, cudaFuncAttributeMaxDynamicSharedMemorySize, GEMM_SMEM);
    cudaFuncSetAttribute(gemm_tc<1>, cudaFuncAttributeMaxDynamicSharedMemorySize, GEMM_SMEM);
    dim3 qkv_grid(EMBED/128, TOKENS/128, 3);
    gemm_tc<0><<<qkv_grid, 256, GEMM_SMEM>>>((const __half*)xt, (const __half*)Weff,
                                             bq, bk, bv, Q, K, V, nullptr);

    // 3) attention
    cudaFuncSetAttribute(attn_tc, cudaFuncAttributeMaxDynamicSharedMemorySize, ATTN_SMEM);
    dim3 agrid(SEQ/128, HEADS, NBATCH);
    attn_tc<<<agrid, 256, ATTN_SMEM>>>((const __half*)Q, (const __half*)K, (const __half*)V, attn);

    // 4) output projection (fp32 out + bias)
    dim3 ogrid(EMBED/128, TOKENS/128, 1);
    gemm_tc<1><<<ogrid, 256, GEMM_SMEM>>>((const __half*)attn,
                                          (const __half*)(Weff + 3*(size_t)(EMBED*EMBED/2)),
                                          bo, bo, bo, nullptr, nullptr, nullptr, out);
}

// round 9
// speedup vs baseline: 17.5204x; 1.0494x over previous
#include <cuda_runtime.h>
#include <cuda_fp16.h>
#include <math.h>
#include <stdint.h>

#define EMBED   1024
#define RANK    8
#define HEADS   16
#define HDIM    64
#define NBATCH  2
#define SEQ     2048
#define TOKENS  (NBATCH*SEQ)
#define LORA_SCALE 2.0f
#define LOG2E   1.44269504088896f

// ---------------- scratch (fp16 pairs stored as uint32) ----------------
__device__ uint32_t g_Weff[4][EMBED*EMBED/2];
__device__ uint32_t g_xt[TOKENS*EMBED/2];
__device__ uint32_t g_Q[TOKENS*EMBED/2];
__device__ uint32_t g_K[TOKENS*EMBED/2];
__device__ uint32_t g_V[TOKENS*EMBED/2];
__device__ uint32_t g_attn[TOKENS*EMBED/2];

// ---------------- helpers ----------------
__device__ __forceinline__ uint32_t pkh2(float a, float b) {
    __half2 h = __floats2half2_rn(a, b);
    return *(uint32_t*)&h;
}
// packed p = exp2(fp16(a,b) - m2), one MUFU for two elements
__device__ __forceinline__ uint32_t pexp2(float a, float b, __half2 m2) {
    __half2 v = __hsub2(__floats2half2_rn(a, b), m2);
    __half2 e = h2exp2(v);
    return *(uint32_t*)&e;
}
__device__ __forceinline__ void mma_f16(float c[4], const uint32_t a[4], const uint32_t b[2]) {
    asm volatile("mma.sync.aligned.m16n8k16.row.col.f32.f16.f16.f32 "
        "{%0,%1,%2,%3}, {%4,%5,%6,%7}, {%8,%9}, {%0,%1,%2,%3};"
        : "+f"(c[0]), "+f"(c[1]), "+f"(c[2]), "+f"(c[3])
        : "r"(a[0]), "r"(a[1]), "r"(a[2]), "r"(a[3]), "r"(b[0]), "r"(b[1]));
}
__device__ __forceinline__ void ldsm4(uint32_t r[4], uint32_t addr) {
    asm volatile("ldmatrix.sync.aligned.m8n8.x4.shared.b16 {%0,%1,%2,%3}, [%4];"
        : "=r"(r[0]), "=r"(r[1]), "=r"(r[2]), "=r"(r[3]) : "r"(addr));
}
__device__ __forceinline__ void ldsm4t(uint32_t r[4], uint32_t addr) {
    asm volatile("ldmatrix.sync.aligned.m8n8.x4.trans.shared.b16 {%0,%1,%2,%3}, [%4];"
        : "=r"(r[0]), "=r"(r[1]), "=r"(r[2]), "=r"(r[3]) : "r"(addr));
}
__device__ __forceinline__ void cp16(uint32_t saddr, const void* gaddr) {
    asm volatile("cp.async.cg.shared.global [%0], [%1], 16;" :: "r"(saddr), "l"(gaddr));
}
#define CP_COMMIT() asm volatile("cp.async.commit_group;")
template<int N> __device__ __forceinline__ void cp_wait() {
    asm volatile("cp.async.wait_group %0;" :: "n"(N));
}

// ---------------- xconv: fp32 -> fp16 ----------------
__global__ void xconv(const float4* __restrict__ in, uint2* __restrict__ out) {
    int i = blockIdx.x * blockDim.x + threadIdx.x;
    float4 v = in[i];
    out[i] = make_uint2(pkh2(v.x, v.y), pkh2(v.z, v.w));
}

// ---------------- fold: Weff[z] = h(wscale * (W + 2 * B @ A)) ----------------
__global__ void fold4_kernel(const float* __restrict__ W0, const float* __restrict__ A0, const float* __restrict__ B0,
                             const float* __restrict__ W1, const float* __restrict__ A1, const float* __restrict__ B1,
                             const float* __restrict__ W2, const float* __restrict__ A2, const float* __restrict__ B2,
                             const float* __restrict__ W3, const float* __restrict__ A3, const float* __restrict__ B3) {
    int z = blockIdx.y;
    const float *W, *A, *B;
    if (z == 0) { W = W0; A = A0; B = B0; }
    else if (z == 1) { W = W1; A = A1; B = B1; }
    else if (z == 2) { W = W2; A = A2; B = B2; }
    else { W = W3; A = A3; B = B3; }
    float wscale = (z == 0) ? 0.125f * LOG2E : 1.0f;
    uint32_t* out = g_Weff[z];
    int idx = blockIdx.x * blockDim.x + threadIdx.x;
    int o = idx >> 9;
    int i = (idx & 511) * 2;
    float s0 = 0.f, s1 = 0.f;
#pragma unroll
    for (int r = 0; r < RANK; r++) {
        float br = B[o*RANK + r];
        s0 = fmaf(br, A[r*EMBED + i],   s0);
        s1 = fmaf(br, A[r*EMBED + i+1], s1);
    }
    out[idx] = pkh2(wscale * (W[o*EMBED + i]   + LORA_SCALE * s0),
                    wscale * (W[o*EMBED + i+1] + LORA_SCALE * s1));
}

// ---------------- fp16 GEMM: C[M,N] = A[M,K] @ Bw[N,K]^T + bias ----------------
// CTA 128x128, 256 threads (8 warps, warp tile 32x64), 5-stage cp.async k32/stage.
#define GSTAGE 20480
#define GNSTG 5
#define GEMM_SMEM (GNSTG*GSTAGE)   // 102400
template<int MODE>
__global__ __launch_bounds__(256, 2)
void gemm_tc(const __half* __restrict__ A, const __half* __restrict__ Wbase,
             const float* __restrict__ bz0, const float* __restrict__ bz1, const float* __restrict__ bz2,
             uint32_t* __restrict__ o0, uint32_t* __restrict__ o1, uint32_t* __restrict__ o2,
             float* __restrict__ ofp) {
    extern __shared__ char smg[];
    const int z = (MODE == 0) ? blockIdx.z : 0;
    const __half* Bw = Wbase + (size_t)z * (EMBED*EMBED);
    const float* bias = (z == 0) ? bz0 : (z == 1) ? bz1 : bz2;
    const float bscale = (MODE == 0 && z == 0) ? 0.125f * LOG2E : 1.0f;
    uint32_t* Ch = (z == 0) ? o0 : (z == 1) ? o1 : o2;

    const int tid = threadIdx.x, warp = tid >> 5, lane = tid & 31;
    const int g = lane >> 2, c = lane & 3;
    const int wm = (warp & 3) * 32, wn = (warp >> 2) * 64;
    const int m0 = blockIdx.y * 128, n0 = blockIdx.x * 128;

    const uint32_t sbase = (uint32_t)__cvta_generic_to_shared(smg);

    auto issue = [&](int s) {
        uint32_t off = sbase + (uint32_t)(s % GNSTG) * GSTAGE;
#pragma unroll
        for (int p = 0; p < 2; p++) {
            int idx = tid + 256*p;
            int row = idx >> 2, part = idx & 3;
            cp16(off + row*80 + part*16,
                 A  + (size_t)(m0 + row)*EMBED + s*32 + part*8);
            cp16(off + 10240 + row*80 + part*16,
                 Bw + (size_t)(n0 + row)*EMBED + s*32 + part*8);
        }
    };

    float acc[2][8][4];
#pragma unroll
    for (int t = 0; t < 2; t++)
#pragma unroll
        for (int j = 0; j < 8; j++)
#pragma unroll
            for (int r = 0; r < 4; r++) acc[t][j][r] = 0.f;

    const int a_row  = lane & 15;
    const int a_half = (lane >> 4) * 16;
    const int b_row  = (lane & 7) + ((lane >> 4) << 3);
    const int b_half = ((lane >> 3) & 1) * 16;

    issue(0); CP_COMMIT();
    issue(1); CP_COMMIT();
    issue(2); CP_COMMIT();
    issue(3); CP_COMMIT();

    for (int s = 0; s < EMBED/32; s++) {
        cp_wait<3>(); __syncthreads();
        if (s + 4 < EMBED/32) issue(s + 4);
        CP_COMMIT();

        uint32_t offA = sbase + (uint32_t)(s % GNSTG) * GSTAGE;
        uint32_t offB = offA + 10240;

#pragma unroll
        for (int kk = 0; kk < 2; kk++) {
            uint32_t af[2][4], bf[8][2];
#pragma unroll
            for (int t = 0; t < 2; t++)
                ldsm4(af[t], offA + (uint32_t)(wm + 16*t + a_row)*80 + a_half + kk*32);
#pragma unroll
            for (int jj = 0; jj < 4; jj++) {
                uint32_t r[4];
                ldsm4(r, offB + (uint32_t)(wn + 16*jj + b_row)*80 + b_half + kk*32);
                bf[2*jj][0] = r[0]; bf[2*jj][1] = r[1];
                bf[2*jj+1][0] = r[2]; bf[2*jj+1][1] = r[3];
            }
#pragma unroll
            for (int t = 0; t < 2; t++)
#pragma unroll
                for (int j = 0; j < 8; j++)
                    mma_f16(acc[t][j], af[t], bf[j]);
        }
    }

    // epilogue
#pragma unroll
    for (int j = 0; j < 8; j++) {
        int col = n0 + wn + 8*j + 2*c;
        float bv0 = bias[col] * bscale, bv1 = bias[col + 1] * bscale;
#pragma unroll
        for (int t = 0; t < 2; t++) {
            int row0 = m0 + wm + 16*t + g;
            float v00 = acc[t][j][0] + bv0, v01 = acc[t][j][1] + bv1;
            float v10 = acc[t][j][2] + bv0, v11 = acc[t][j][3] + bv1;
            if (MODE == 1) {
                *(float2*)(ofp + (size_t)row0*EMBED + col)     = make_float2(v00, v01);
                *(float2*)(ofp + (size_t)(row0+8)*EMBED + col) = make_float2(v10, v11);
            } else {
                Ch[((size_t)row0*EMBED + col) >> 1]     = pkh2(v00, v01);
                Ch[((size_t)(row0+8)*EMBED + col) >> 1] = pkh2(v10, v11);
            }
        }
    }
}

// ---------------- flash attention, fp16 mma, pipelined S, f16x2 softmax ----------------
// 128 q/CTA, 8 warps (16 q each), key tiles of 64, 4-slot K/V ring.
#define KOB(s)  ((uint32_t)(s)*9216u)
#define VOB(s)  (36864u + (uint32_t)(s)*9216u)
#define QO      73728u
#define ATTN_SMEM (73728 + 18432)   // 92160
#define NT (SEQ/64)

__global__ __launch_bounds__(256, 2)
void attn_tc(const __half* __restrict__ Qg, const __half* __restrict__ Kg,
             const __half* __restrict__ Vg, uint32_t* __restrict__ Og) {
    extern __shared__ char sma[];
    const uint32_t sbase = (uint32_t)__cvta_generic_to_shared(sma);

    const int qt = blockIdx.x, h = blockIdx.y, nb = blockIdx.z;
    const int tid = threadIdx.x, warp = tid >> 5, lane = tid & 31;
    const int g = lane >> 2, c = lane & 3;
    const int q0 = warp * 16;
    const int base_q = nb*SEQ + qt*128;
    const int col0 = h * HDIM;

    auto kvissue = [&](int kt) {
        int s = kt & 3;
        int base_k = nb*SEQ + kt*64;
#pragma unroll
        for (int p = 0; p < 2; p++) {
            int idx = tid + 256*p;
            int row = idx >> 3, q = idx & 7;
            cp16(sbase + KOB(s) + row*144 + q*16,
                 Kg + (size_t)(base_k + row)*EMBED + col0 + 8*q);
        }
#pragma unroll
        for (int p = 0; p < 2; p++) {
            int idx = tid + 256*p;
            int row = idx >> 3, q = idx & 7;
            cp16(sbase + VOB(s) + row*144 + q*16,
                 Vg + (size_t)(base_k + row)*EMBED + col0 + 8*q);
        }
    };

    // Q tile (128 rows x 64 halves), stride 144B
#pragma unroll
    for (int p = 0; p < 4; p++) {
        int idx = tid + 256*p;
        int row = idx >> 3, q = idx & 7;
        cp16(sbase + QO + row*144 + q*16,
             Qg + (size_t)(base_q + row)*EMBED + col0 + 8*q);
    }
    CP_COMMIT();
    kvissue(0); CP_COMMIT();
    kvissue(1); CP_COMMIT();
    kvissue(2); CP_COMMIT();

    const int b_row  = (lane & 7) + ((lane >> 4) << 3);
    const int b_half = ((lane >> 3) & 1) * 16;
    const int v_row  = (lane & 7) + (((lane >> 3) & 1) << 3);
    const int v_half = (lane >> 4) * 16;

    cp_wait<3>(); __syncthreads();   // Q done
    uint32_t qf[4][4];
#pragma unroll
    for (int kk = 0; kk < 4; kk++)
        ldsm4(qf[kk], sbase + QO + (uint32_t)(q0 + (lane & 15))*144 + (lane >> 4)*16 + kk*32);

    float sf[8][4];
    auto do_S = [&](uint32_t Ko) {
#pragma unroll
        for (int j = 0; j < 8; j++)
#pragma unroll
            for (int r = 0; r < 4; r++) sf[j][r] = 0.f;
#pragma unroll
        for (int kk = 0; kk < 4; kk++) {
            uint32_t bf[8][2];
#pragma unroll
            for (int jj = 0; jj < 4; jj++) {
                uint32_t r[4];
                ldsm4(r, sbase + Ko + (uint32_t)(16*jj + b_row)*144 + b_half + kk*32);
                bf[2*jj][0] = r[0]; bf[2*jj][1] = r[1];
                bf[2*jj+1][0] = r[2]; bf[2*jj+1][1] = r[3];
            }
#pragma unroll
            for (int j = 0; j < 8; j++)
                mma_f16(sf[j], qf[kk], bf[j]);
        }
    };

    cp_wait<2>(); __syncthreads();   // kv0 done
    do_S(KOB(0));                    // S(0)

    float of[8][4], of_l[4];
#pragma unroll
    for (int j = 0; j < 8; j++)
#pragma unroll
        for (int r = 0; r < 4; r++) of[j][r] = 0.f;
#pragma unroll
    for (int r = 0; r < 4; r++) of_l[r] = 0.f;
    float m_lo = -1e30f, m_hi = -1e30f;
    const uint32_t ones2 = 0x3C003C00u;

    for (int kt = 0; kt < NT; kt++) {
        // ---- softmax(kt) on sf (base-2 domain, f16x2 exp) ----
        float mx_lo = -1e30f, mx_hi = -1e30f;
#pragma unroll
        for (int j = 0; j < 8; j++) {
            mx_lo = fmaxf(mx_lo, fmaxf(sf[j][0], sf[j][1]));
            mx_hi = fmaxf(mx_hi, fmaxf(sf[j][2], sf[j][3]));
        }
        mx_lo = fmaxf(mx_lo, __shfl_xor_sync(0xffffffffu, mx_lo, 1));
        mx_lo = fmaxf(mx_lo, __shfl_xor_sync(0xffffffffu, mx_lo, 2));
        mx_hi = fmaxf(mx_hi, __shfl_xor_sync(0xffffffffu, mx_hi, 1));
        mx_hi = fmaxf(mx_hi, __shfl_xor_sync(0xffffffffu, mx_hi, 2));

        float mn_lo = fmaxf(m_lo, mx_lo);
        float mn_hi = fmaxf(m_hi, mx_hi);
        float alpha_lo = exp2f(m_lo - mn_lo);
        float alpha_hi = exp2f(m_hi - mn_hi);
        m_lo = mn_lo; m_hi = mn_hi;

        __half2 ml2 = __float2half2_rn(mn_lo);
        __half2 mh2 = __float2half2_rn(mn_hi);
        uint32_t pa[4][4];
#pragma unroll
        for (int kk = 0; kk < 4; kk++) {
            pa[kk][0] = pexp2(sf[2*kk][0],   sf[2*kk][1],   ml2);
            pa[kk][1] = pexp2(sf[2*kk][2],   sf[2*kk][3],   mh2);
            pa[kk][2] = pexp2(sf[2*kk+1][0], sf[2*kk+1][1], ml2);
            pa[kk][3] = pexp2(sf[2*kk+1][2], sf[2*kk+1][3], mh2);
        }

        // ---- advance pipeline: kv(kt+1) ready; refill slot; S(kt+1) ----
        cp_wait<1>(); __syncthreads();       // kv(kt+1) complete; all warps past PV(kt-1)
        if (kt + 3 < NT) kvissue(kt + 3);
        CP_COMMIT();
        if (kt + 1 < NT) do_S(KOB((kt + 1) & 3));   // sf <- S(kt+1), overlaps PV(kt)

        // ---- O = O*alpha + P @ V ; l via ones-column mma ----
#pragma unroll
        for (int j = 0; j < 8; j++) {
            of[j][0] *= alpha_lo; of[j][1] *= alpha_lo;
            of[j][2] *= alpha_hi; of[j][3] *= alpha_hi;
        }
        of_l[0] *= alpha_lo; of_l[1] *= alpha_lo;
        of_l[2] *= alpha_hi; of_l[3] *= alpha_hi;

        const uint32_t Vo = VOB(kt & 3);
#pragma unroll
        for (int kk = 0; kk < 4; kk++) {
#pragma unroll
            for (int dd = 0; dd < 4; dd++) {
                uint32_t r[4];
                ldsm4t(r, sbase + Vo + (uint32_t)(kk*16 + v_row)*144 + dd*32 + v_half);
                uint32_t b0[2] = { r[0], r[1] };
                uint32_t b1[2] = { r[2], r[3] };
                mma_f16(of[2*dd],   pa[kk], b0);
                mma_f16(of[2*dd+1], pa[kk], b1);
            }
            uint32_t ob[2] = { ones2, ones2 };
            mma_f16(of_l, pa[kk], ob);
        }
    }

    // ---- epilogue: fp16 out (consumed by o-proj GEMM) ----
    float il_lo = 1.f / of_l[0], il_hi = 1.f / of_l[2];
#pragma unroll
    for (int dj = 0; dj < 8; dj++) {
        int col = col0 + 8*dj + 2*c;
        Og[((size_t)(base_q + q0 + g)*EMBED + col) >> 1]     = pkh2(of[dj][0]*il_lo, of[dj][1]*il_lo);
        Og[((size_t)(base_q + q0 + g + 8)*EMBED + col) >> 1] = pkh2(of[dj][2]*il_hi, of[dj][3]*il_hi);
    }
}

// ---------------- launch ----------------
extern "C" void kernel_launch(void* const* d_in, const int* in_sizes, int n_in,
                              void* d_out, int out_size) {
    const float* x  = (const float*)d_in[0];
    const float* Wq = (const float*)d_in[1];
    const float* bq = (const float*)d_in[2];
    const float* Aq = (const float*)d_in[3];
    const float* Bq = (const float*)d_in[4];
    const float* Wk = (const float*)d_in[5];
    const float* bk = (const float*)d_in[6];
    const float* Ak = (const float*)d_in[7];
    const float* Bk = (const float*)d_in[8];
    const float* Wv = (const float*)d_in[9];
    const float* bv = (const float*)d_in[10];
    const float* Av = (const float*)d_in[11];
    const float* Bv = (const float*)d_in[12];
    const float* Wo = (const float*)d_in[13];
    const float* bo = (const float*)d_in[14];
    const float* Ao = (const float*)d_in[15];
    const float* Bo = (const float*)d_in[16];
    float* out = (float*)d_out;

    uint32_t *Weff, *xt, *Q, *K, *V, *attn;
    cudaGetSymbolAddress((void**)&Weff, g_Weff);
    cudaGetSymbolAddress((void**)&xt, g_xt);
    cudaGetSymbolAddress((void**)&Q, g_Q);
    cudaGetSymbolAddress((void**)&K, g_K);
    cudaGetSymbolAddress((void**)&V, g_V);
    cudaGetSymbolAddress((void**)&attn, g_attn);

    // 0) x -> fp16
    xconv<<<TOKENS*EMBED/4/256, 256>>>((const float4*)x, (uint2*)xt);

    // 1) fold LoRA into effective fp16 weights (Q pre-scaled by 0.125*log2e)
    dim3 fgrid(EMBED*EMBED/2/256, 4);
    fold4_kernel<<<fgrid, 256>>>(Wq, Aq, Bq, Wk, Ak, Bk, Wv, Av, Bv, Wo, Ao, Bo);

    // 2) fused Q/K/V projections
    cudaFuncSetAttribute(gemm_tc<0>, cudaFuncAttributeMaxDynamicSharedMemorySize, GEMM_SMEM);
    cudaFuncSetAttribute(gemm_tc<1>, cudaFuncAttributeMaxDynamicSharedMemorySize, GEMM_SMEM);
    dim3 qkv_grid(EMBED/128, TOKENS/128, 3);
    gemm_tc<0><<<qkv_grid, 256, GEMM_SMEM>>>((const __half*)xt, (const __half*)Weff,
                                             bq, bk, bv, Q, K, V, nullptr);

    // 3) attention
    cudaFuncSetAttribute(attn_tc, cudaFuncAttributeMaxDynamicSharedMemorySize, ATTN_SMEM);
    dim3 agrid(SEQ/128, HEADS, NBATCH);
    attn_tc<<<agrid, 256, ATTN_SMEM>>>((const __half*)Q, (const __half*)K, (const __half*)V, attn);

    // 4) output projection (fp32 out + bias)
    dim3 ogrid(EMBED/128, TOKENS/128, 1);
    gemm_tc<1><<<ogrid, 256, GEMM_SMEM>>>((const __half*)attn,
                                          (const __half*)(Weff + 3*(size_t)(EMBED*EMBED/2)),
                                          bo, bo, bo, nullptr, nullptr, nullptr, out);
}

// round 10
// speedup vs baseline: 18.4552x; 1.0534x over previous
#include <cuda_runtime.h>
#include <cuda_fp16.h>
#include <math.h>
#include <stdint.h>

#define EMBED   1024
#define RANK    8
#define HEADS   16
#define HDIM    64
#define NBATCH  2
#define SEQ     2048
#define TOKENS  (NBATCH*SEQ)
#define LORA_SCALE 2.0f
#define LOG2E   1.44269504088896f

// ---------------- scratch (fp16 pairs stored as uint32) ----------------
__device__ uint32_t g_Weff[4][EMBED*EMBED/2];
__device__ uint32_t g_xt[TOKENS*EMBED/2];
__device__ uint32_t g_Q[TOKENS*EMBED/2];
__device__ uint32_t g_K[TOKENS*EMBED/2];
__device__ uint32_t g_V[TOKENS*EMBED/2];
__device__ uint32_t g_attn[TOKENS*EMBED/2];

// ---------------- helpers ----------------
__device__ __forceinline__ uint32_t pkh2(float a, float b) {
    __half2 h = __floats2half2_rn(a, b);
    return *(uint32_t*)&h;
}
__device__ __forceinline__ uint32_t pexp2(float a, float b, __half2 m2) {
    __half2 v = __hsub2(__floats2half2_rn(a, b), m2);
    __half2 e = h2exp2(v);
    return *(uint32_t*)&e;
}
__device__ __forceinline__ void mma_f16(float c[4], const uint32_t a[4], const uint32_t b[2]) {
    asm volatile("mma.sync.aligned.m16n8k16.row.col.f32.f16.f16.f32 "
        "{%0,%1,%2,%3}, {%4,%5,%6,%7}, {%8,%9}, {%0,%1,%2,%3};"
        : "+f"(c[0]), "+f"(c[1]), "+f"(c[2]), "+f"(c[3])
        : "r"(a[0]), "r"(a[1]), "r"(a[2]), "r"(a[3]), "r"(b[0]), "r"(b[1]));
}
__device__ __forceinline__ void ldsm4(uint32_t r[4], uint32_t addr) {
    asm volatile("ldmatrix.sync.aligned.m8n8.x4.shared.b16 {%0,%1,%2,%3}, [%4];"
        : "=r"(r[0]), "=r"(r[1]), "=r"(r[2]), "=r"(r[3]) : "r"(addr));
}
__device__ __forceinline__ void ldsm4t(uint32_t r[4], uint32_t addr) {
    asm volatile("ldmatrix.sync.aligned.m8n8.x4.trans.shared.b16 {%0,%1,%2,%3}, [%4];"
        : "=r"(r[0]), "=r"(r[1]), "=r"(r[2]), "=r"(r[3]) : "r"(addr));
}
__device__ __forceinline__ void cp16(uint32_t saddr, const void* gaddr) {
    asm volatile("cp.async.cg.shared.global [%0], [%1], 16;" :: "r"(saddr), "l"(gaddr));
}
#define CP_COMMIT() asm volatile("cp.async.commit_group;")
template<int N> __device__ __forceinline__ void cp_wait() {
    asm volatile("cp.async.wait_group %0;" :: "n"(N));
}

// ---------------- xconv: fp32 -> fp16 ----------------
__global__ void xconv(const float4* __restrict__ in, uint2* __restrict__ out) {
    int i = blockIdx.x * blockDim.x + threadIdx.x;
    float4 v = in[i];
    out[i] = make_uint2(pkh2(v.x, v.y), pkh2(v.z, v.w));
}

// ---------------- fold: Weff[z] = h(wscale * (W + 2 * B @ A)) ----------------
__global__ void fold4_kernel(const float* __restrict__ W0, const float* __restrict__ A0, const float* __restrict__ B0,
                             const float* __restrict__ W1, const float* __restrict__ A1, const float* __restrict__ B1,
                             const float* __restrict__ W2, const float* __restrict__ A2, const float* __restrict__ B2,
                             const float* __restrict__ W3, const float* __restrict__ A3, const float* __restrict__ B3) {
    int z = blockIdx.y;
    const float *W, *A, *B;
    if (z == 0) { W = W0; A = A0; B = B0; }
    else if (z == 1) { W = W1; A = A1; B = B1; }
    else if (z == 2) { W = W2; A = A2; B = B2; }
    else { W = W3; A = A3; B = B3; }
    float wscale = (z == 0) ? 0.125f * LOG2E : 1.0f;
    uint32_t* out = g_Weff[z];
    int idx = blockIdx.x * blockDim.x + threadIdx.x;
    int o = idx >> 9;
    int i = (idx & 511) * 2;
    float s0 = 0.f, s1 = 0.f;
#pragma unroll
    for (int r = 0; r < RANK; r++) {
        float br = B[o*RANK + r];
        s0 = fmaf(br, A[r*EMBED + i],   s0);
        s1 = fmaf(br, A[r*EMBED + i+1], s1);
    }
    out[idx] = pkh2(wscale * (W[o*EMBED + i]   + LORA_SCALE * s0),
                    wscale * (W[o*EMBED + i+1] + LORA_SCALE * s1));
}

// ---------------- fp16 GEMM: C[M,N] = A[M,K] @ Bw[N,K]^T + bias ----------------
// CTA 128x128, 256 threads (8 warps, warp tile 32x64), 5-stage cp.async k32/stage.
#define GSTAGE 20480
#define GNSTG 5
#define GEMM_SMEM (GNSTG*GSTAGE)   // 102400
template<int MODE>
__global__ __launch_bounds__(256, 2)
void gemm_tc(const __half* __restrict__ A, const __half* __restrict__ Wbase,
             const float* __restrict__ bz0, const float* __restrict__ bz1, const float* __restrict__ bz2,
             uint32_t* __restrict__ o0, uint32_t* __restrict__ o1, uint32_t* __restrict__ o2,
             float* __restrict__ ofp) {
    extern __shared__ char smg[];
    const int z = (MODE == 0) ? blockIdx.z : 0;
    const __half* Bw = Wbase + (size_t)z * (EMBED*EMBED);
    const float* bias = (z == 0) ? bz0 : (z == 1) ? bz1 : bz2;
    const float bscale = (MODE == 0 && z == 0) ? 0.125f * LOG2E : 1.0f;
    uint32_t* Ch = (z == 0) ? o0 : (z == 1) ? o1 : o2;

    const int tid = threadIdx.x, warp = tid >> 5, lane = tid & 31;
    const int g = lane >> 2, c = lane & 3;
    const int wm = (warp & 3) * 32, wn = (warp >> 2) * 64;
    const int m0 = blockIdx.y * 128, n0 = blockIdx.x * 128;

    const uint32_t sbase = (uint32_t)__cvta_generic_to_shared(smg);

    auto issue = [&](int s) {
        uint32_t off = sbase + (uint32_t)(s % GNSTG) * GSTAGE;
#pragma unroll
        for (int p = 0; p < 2; p++) {
            int idx = tid + 256*p;
            int row = idx >> 2, part = idx & 3;
            cp16(off + row*80 + part*16,
                 A  + (size_t)(m0 + row)*EMBED + s*32 + part*8);
            cp16(off + 10240 + row*80 + part*16,
                 Bw + (size_t)(n0 + row)*EMBED + s*32 + part*8);
        }
    };

    float acc[2][8][4];
#pragma unroll
    for (int t = 0; t < 2; t++)
#pragma unroll
        for (int j = 0; j < 8; j++)
#pragma unroll
            for (int r = 0; r < 4; r++) acc[t][j][r] = 0.f;

    const int a_row  = lane & 15;
    const int a_half = (lane >> 4) * 16;
    const int b_row  = (lane & 7) + ((lane >> 4) << 3);
    const int b_half = ((lane >> 3) & 1) * 16;

    issue(0); CP_COMMIT();
    issue(1); CP_COMMIT();
    issue(2); CP_COMMIT();
    issue(3); CP_COMMIT();

    for (int s = 0; s < EMBED/32; s++) {
        cp_wait<3>(); __syncthreads();
        if (s + 4 < EMBED/32) issue(s + 4);
        CP_COMMIT();

        uint32_t offA = sbase + (uint32_t)(s % GNSTG) * GSTAGE;
        uint32_t offB = offA + 10240;

#pragma unroll
        for (int kk = 0; kk < 2; kk++) {
            uint32_t af[2][4], bf[8][2];
#pragma unroll
            for (int t = 0; t < 2; t++)
                ldsm4(af[t], offA + (uint32_t)(wm + 16*t + a_row)*80 + a_half + kk*32);
#pragma unroll
            for (int jj = 0; jj < 4; jj++) {
                uint32_t r[4];
                ldsm4(r, offB + (uint32_t)(wn + 16*jj + b_row)*80 + b_half + kk*32);
                bf[2*jj][0] = r[0]; bf[2*jj][1] = r[1];
                bf[2*jj+1][0] = r[2]; bf[2*jj+1][1] = r[3];
            }
#pragma unroll
            for (int t = 0; t < 2; t++)
#pragma unroll
                for (int j = 0; j < 8; j++)
                    mma_f16(acc[t][j], af[t], bf[j]);
        }
    }

    // epilogue
#pragma unroll
    for (int j = 0; j < 8; j++) {
        int col = n0 + wn + 8*j + 2*c;
        float bv0 = bias[col] * bscale, bv1 = bias[col + 1] * bscale;
#pragma unroll
        for (int t = 0; t < 2; t++) {
            int row0 = m0 + wm + 16*t + g;
            float v00 = acc[t][j][0] + bv0, v01 = acc[t][j][1] + bv1;
            float v10 = acc[t][j][2] + bv0, v11 = acc[t][j][3] + bv1;
            if (MODE == 1) {
                *(float2*)(ofp + (size_t)row0*EMBED + col)     = make_float2(v00, v01);
                *(float2*)(ofp + (size_t)(row0+8)*EMBED + col) = make_float2(v10, v11);
            } else {
                Ch[((size_t)row0*EMBED + col) >> 1]     = pkh2(v00, v01);
                Ch[((size_t)(row0+8)*EMBED + col) >> 1] = pkh2(v10, v11);
            }
        }
    }
}

// ---------------- flash attention: 4 small CTAs/SM, 1 barrier/tile ----------------
// 64 q/CTA, 4 warps (16 q each), key tiles of 64, 2-slot K/V ring.
// smem: K 2x[64][144B], V 2x[64][144B], Q [64][144B] = 46080 B -> 4 CTAs/SM
#define KOB(s)  ((uint32_t)(s)*9216u)
#define VOB(s)  (18432u + (uint32_t)(s)*9216u)
#define QO      36864u
#define ATTN_SMEM (36864 + 9216)   // 46080
#define NT (SEQ/64)

__global__ __launch_bounds__(128, 4)
void attn_tc(const __half* __restrict__ Qg, const __half* __restrict__ Kg,
             const __half* __restrict__ Vg, uint32_t* __restrict__ Og) {
    extern __shared__ char sma[];
    const uint32_t sbase = (uint32_t)__cvta_generic_to_shared(sma);

    const int qt = blockIdx.x, h = blockIdx.y, nb = blockIdx.z;
    const int tid = threadIdx.x, warp = tid >> 5, lane = tid & 31;
    const int g = lane >> 2, c = lane & 3;
    const int q0 = warp * 16;
    const int base_q = nb*SEQ + qt*64;
    const int col0 = h * HDIM;

    auto kvissue = [&](int kt) {
        int s = kt & 1;
        int base_k = nb*SEQ + kt*64;
#pragma unroll
        for (int p = 0; p < 4; p++) {
            int idx = tid + 128*p;            // 0..511
            int row = idx >> 3, q = idx & 7;
            cp16(sbase + KOB(s) + row*144 + q*16,
                 Kg + (size_t)(base_k + row)*EMBED + col0 + 8*q);
        }
#pragma unroll
        for (int p = 0; p < 4; p++) {
            int idx = tid + 128*p;
            int row = idx >> 3, q = idx & 7;
            cp16(sbase + VOB(s) + row*144 + q*16,
                 Vg + (size_t)(base_k + row)*EMBED + col0 + 8*q);
        }
    };

    // Q tile (64 rows x 64 halves), stride 144B
#pragma unroll
    for (int p = 0; p < 4; p++) {
        int idx = tid + 128*p;                // 0..511
        int row = idx >> 3, q = idx & 7;
        cp16(sbase + QO + row*144 + q*16,
             Qg + (size_t)(base_q + row)*EMBED + col0 + 8*q);
    }
    CP_COMMIT();
    kvissue(0); CP_COMMIT();

    const int b_row  = (lane & 7) + ((lane >> 4) << 3);
    const int b_half = ((lane >> 3) & 1) * 16;
    const int v_row  = (lane & 7) + (((lane >> 3) & 1) << 3);
    const int v_half = (lane >> 4) * 16;

    cp_wait<0>(); __syncthreads();   // Q + kv0 ready
    uint32_t qf[4][4];
#pragma unroll
    for (int kk = 0; kk < 4; kk++)
        ldsm4(qf[kk], sbase + QO + (uint32_t)(q0 + (lane & 15))*144 + (lane >> 4)*16 + kk*32);

    float of[8][4], of_l[4];
#pragma unroll
    for (int j = 0; j < 8; j++)
#pragma unroll
        for (int r = 0; r < 4; r++) of[j][r] = 0.f;
#pragma unroll
    for (int r = 0; r < 4; r++) of_l[r] = 0.f;
    float m_lo = -1e30f, m_hi = -1e30f;
    const uint32_t ones2 = 0x3C003C00u;

    for (int kt = 0; kt < NT; kt++) {
        // prefetch next tile into the slot freed at end of previous iteration
        if (kt + 1 < NT) { kvissue(kt + 1); CP_COMMIT(); }
        const uint32_t Ko = KOB(kt & 1);
        const uint32_t Vo = VOB(kt & 1);

        // ---- S = Q @ K^T ----
        float sf[8][4];
#pragma unroll
        for (int j = 0; j < 8; j++)
#pragma unroll
            for (int r = 0; r < 4; r++) sf[j][r] = 0.f;
#pragma unroll
        for (int kk = 0; kk < 4; kk++) {
            uint32_t bf[8][2];
#pragma unroll
            for (int jj = 0; jj < 4; jj++) {
                uint32_t r[4];
                ldsm4(r, sbase + Ko + (uint32_t)(16*jj + b_row)*144 + b_half + kk*32);
                bf[2*jj][0] = r[0]; bf[2*jj][1] = r[1];
                bf[2*jj+1][0] = r[2]; bf[2*jj+1][1] = r[3];
            }
#pragma unroll
            for (int j = 0; j < 8; j++)
                mma_f16(sf[j], qf[kk], bf[j]);
        }

        // ---- online softmax (base-2, f16x2 exp) ----
        float mx_lo = -1e30f, mx_hi = -1e30f;
#pragma unroll
        for (int j = 0; j < 8; j++) {
            mx_lo = fmaxf(mx_lo, fmaxf(sf[j][0], sf[j][1]));
            mx_hi = fmaxf(mx_hi, fmaxf(sf[j][2], sf[j][3]));
        }
        mx_lo = fmaxf(mx_lo, __shfl_xor_sync(0xffffffffu, mx_lo, 1));
        mx_lo = fmaxf(mx_lo, __shfl_xor_sync(0xffffffffu, mx_lo, 2));
        mx_hi = fmaxf(mx_hi, __shfl_xor_sync(0xffffffffu, mx_hi, 1));
        mx_hi = fmaxf(mx_hi, __shfl_xor_sync(0xffffffffu, mx_hi, 2));

        bool need_rescale = (mx_lo > m_lo) || (mx_hi > m_hi);
        float mn_lo = fmaxf(m_lo, mx_lo);
        float mn_hi = fmaxf(m_hi, mx_hi);

        if (need_rescale) {
            float alpha_lo = exp2f(m_lo - mn_lo);
            float alpha_hi = exp2f(m_hi - mn_hi);
#pragma unroll
            for (int j = 0; j < 8; j++) {
                of[j][0] *= alpha_lo; of[j][1] *= alpha_lo;
                of[j][2] *= alpha_hi; of[j][3] *= alpha_hi;
            }
            of_l[0] *= alpha_lo; of_l[1] *= alpha_lo;
            of_l[2] *= alpha_hi; of_l[3] *= alpha_hi;
            m_lo = mn_lo; m_hi = mn_hi;
        }

        __half2 ml2 = __float2half2_rn(mn_lo);
        __half2 mh2 = __float2half2_rn(mn_hi);
        uint32_t pa[4][4];
#pragma unroll
        for (int kk = 0; kk < 4; kk++) {
            pa[kk][0] = pexp2(sf[2*kk][0],   sf[2*kk][1],   ml2);
            pa[kk][1] = pexp2(sf[2*kk][2],   sf[2*kk][3],   mh2);
            pa[kk][2] = pexp2(sf[2*kk+1][0], sf[2*kk+1][1], ml2);
            pa[kk][3] = pexp2(sf[2*kk+1][2], sf[2*kk+1][3], mh2);
        }

        // ---- O += P @ V ; l via ones-column mma ----
#pragma unroll
        for (int kk = 0; kk < 4; kk++) {
#pragma unroll
            for (int dd = 0; dd < 4; dd++) {
                uint32_t r[4];
                ldsm4t(r, sbase + Vo + (uint32_t)(kk*16 + v_row)*144 + dd*32 + v_half);
                uint32_t b0[2] = { r[0], r[1] };
                uint32_t b1[2] = { r[2], r[3] };
                mma_f16(of[2*dd],   pa[kk], b0);
                mma_f16(of[2*dd+1], pa[kk], b1);
            }
            uint32_t ob[2] = { ones2, ones2 };
            mma_f16(of_l, pa[kk], ob);
        }

        // kv(kt+1) landed (this thread) + all warps done reading slot kt&1
        cp_wait<0>();
        __syncthreads();
    }

    // ---- epilogue: fp16 out (consumed by o-proj GEMM) ----
    float il_lo = 1.f / of_l[0], il_hi = 1.f / of_l[2];
#pragma unroll
    for (int dj = 0; dj < 8; dj++) {
        int col = col0 + 8*dj + 2*c;
        Og[((size_t)(base_q + q0 + g)*EMBED + col) >> 1]     = pkh2(of[dj][0]*il_lo, of[dj][1]*il_lo);
        Og[((size_t)(base_q + q0 + g + 8)*EMBED + col) >> 1] = pkh2(of[dj][2]*il_hi, of[dj][3]*il_hi);
    }
}

// ---------------- launch ----------------
extern "C" void kernel_launch(void* const* d_in, const int* in_sizes, int n_in,
                              void* d_out, int out_size) {
    const float* x  = (const float*)d_in[0];
    const float* Wq = (const float*)d_in[1];
    const float* bq = (const float*)d_in[2];
    const float* Aq = (const float*)d_in[3];
    const float* Bq = (const float*)d_in[4];
    const float* Wk = (const float*)d_in[5];
    const float* bk = (const float*)d_in[6];
    const float* Ak = (const float*)d_in[7];
    const float* Bk = (const float*)d_in[8];
    const float* Wv = (const float*)d_in[9];
    const float* bv = (const float*)d_in[10];
    const float* Av = (const float*)d_in[11];
    const float* Bv = (const float*)d_in[12];
    const float* Wo = (const float*)d_in[13];
    const float* bo = (const float*)d_in[14];
    const float* Ao = (const float*)d_in[15];
    const float* Bo = (const float*)d_in[16];
    float* out = (float*)d_out;

    uint32_t *Weff, *xt, *Q, *K, *V, *attn;
    cudaGetSymbolAddress((void**)&Weff, g_Weff);
    cudaGetSymbolAddress((void**)&xt, g_xt);
    cudaGetSymbolAddress((void**)&Q, g_Q);
    cudaGetSymbolAddress((void**)&K, g_K);
    cudaGetSymbolAddress((void**)&V, g_V);
    cudaGetSymbolAddress((void**)&attn, g_attn);

    // 0) x -> fp16
    xconv<<<TOKENS*EMBED/4/256, 256>>>((const float4*)x, (uint2*)xt);

    // 1) fold LoRA into effective fp16 weights (Q pre-scaled by 0.125*log2e)
    dim3 fgrid(EMBED*EMBED/2/256, 4);
    fold4_kernel<<<fgrid, 256>>>(Wq, Aq, Bq, Wk, Ak, Bk, Wv, Av, Bv, Wo, Ao, Bo);

    // 2) fused Q/K/V projections
    cudaFuncSetAttribute(gemm_tc<0>, cudaFuncAttributeMaxDynamicSharedMemorySize, GEMM_SMEM);
    cudaFuncSetAttribute(gemm_tc<1>, cudaFuncAttributeMaxDynamicSharedMemorySize, GEMM_SMEM);
    dim3 qkv_grid(EMBED/128, TOKENS/128, 3);
    gemm_tc<0><<<qkv_grid, 256, GEMM_SMEM>>>((const __half*)xt, (const __half*)Weff,
                                             bq, bk, bv, Q, K, V, nullptr);

    // 3) attention (64 q per 128-thread CTA, 4 CTAs/SM)
    dim3 agrid(SEQ/64, HEADS, NBATCH);
    attn_tc<<<agrid, 128, ATTN_SMEM>>>((const __half*)Q, (const __half*)K, (const __half*)V, attn);

    // 4) output projection (fp32 out + bias)
    dim3 ogrid(EMBED/128, TOKENS/128, 1);
    gemm_tc<1><<<ogrid, 256, GEMM_SMEM>>>((const __half*)attn,
                                          (const __half*)(Weff + 3*(size_t)(EMBED*EMBED/2)),
                                          bo, bo, bo, nullptr, nullptr, nullptr, out);
}